// round 2
// baseline (speedup 1.0000x reference)
#include <cuda_runtime.h>
#include <math.h>

#define NB 8
#define NG 32768
#define NA 64
#define ND 128
#define GT 64
#define NTILES (NB*(NG/GT))   // 4096
#define BSTRIDE 132

typedef unsigned long long u64;

// ---- scratch (static device allocations are allowed) ----
__device__ float g_gto[NB*NG*NA];        // 64 MB
__device__ float g_mo [NB*NG*ND];        // 128 MB
__device__ float g_gnorm2 [NB*NA];
__device__ float g_monorm2[NB*ND];
__device__ float g_ceff[NB*NA*ND];
__device__ float g_invmo[NB*ND];
__device__ float g_u[ND];
__device__ float g_t[ND];
__device__ float g_W1t[ND*ND];           // layer-1 weights, [d][e]
__device__ float g_W2t[ND*ND];           // layer-2 weights, [d][e]

// ---------- packed f32x2 helpers ----------
static __device__ __forceinline__ u64 dup2(float x) {
    u64 r; asm("mov.b64 %0, {%1, %1};" : "=l"(r) : "f"(x)); return r;
}
static __device__ __forceinline__ void ffma2(u64& acc, u64 a, u64 b) {
    asm("fma.rn.f32x2 %0, %1, %2, %0;" : "+l"(acc) : "l"(a), "l"(b));
}
static __device__ __forceinline__ float2 up2(u64 v) {
    float2 f; asm("mov.b64 {%0, %1}, %2;" : "=f"(f.x), "=f"(f.y) : "l"(v)); return f;
}

// Packed GEMM core: 4 rows (g0..g0+3) x 8 cols (c0..c0+7) per thread.
// A: [g][astride] activations (read along k), W: [k][ND] weights (cols contiguous).
// acc[r][jp] packs output cols (c0+2*jp, c0+2*jp+1).
static __device__ __forceinline__ void gemm_core(
    const float* __restrict__ A, int astride,
    const float* __restrict__ W,
    u64 acc[4][4], int g0, int c0, int K4)
{
    #pragma unroll 4
    for (int k4 = 0; k4 < K4; k4++) {
        u64 w[4][4];
        #pragma unroll
        for (int k = 0; k < 4; k++) {
            const u64* wr = (const u64*)(W + (4*k4 + k)*ND + c0);
            w[k][0] = wr[0]; w[k][1] = wr[1]; w[k][2] = wr[2]; w[k][3] = wr[3];
        }
        #pragma unroll
        for (int r = 0; r < 4; r++) {
            float4 v = *(const float4*)(A + (g0 + r)*astride + 4*k4);
            u64 d0 = dup2(v.x), d1 = dup2(v.y), d2 = dup2(v.z), d3 = dup2(v.w);
            #pragma unroll
            for (int jp = 0; jp < 4; jp++) {
                ffma2(acc[r][jp], d0, w[0][jp]);
                ffma2(acc[r][jp], d1, w[1][jp]);
                ffma2(acc[r][jp], d2, w[2][jp]);
                ffma2(acc[r][jp], d3, w[3][jp]);
            }
        }
    }
}

// ---------- fast exp(-x) via FMA-pipe poly (no MUFU) ----------
static __device__ __forceinline__ float fast_expneg(float x) {
    // 2^t with t = -x*log2(e), t clamped to [-126, 0]
    float t = fmaxf(-x * 1.4426950408889634f, -126.0f);
    float k = t + 12582912.0f;                 // round-to-nearest via magic
    int   i = __float_as_int(k);
    float n = k - 12582912.0f;
    float f = t - n;                            // [-0.5, 0.5]
    float p = fmaf(f, 1.3333558e-3f, 9.6181291e-3f);
    p = fmaf(f, p, 5.5504109e-2f);
    p = fmaf(f, p, 2.4022651e-1f);
    p = fmaf(f, p, 6.9314718e-1f);
    p = fmaf(f, p, 1.0f);
    float s = __int_as_float((i + (127 - 0x4B400000)) << 23);   // 2^n
    return p * s;
}

// ---------- init: zero accumulators, seed output with W_prop_b ----------
__global__ void initK(float* out, const float* __restrict__ wpb) {
    int i = blockIdx.x * blockDim.x + threadIdx.x;
    if (i < NB*NA) g_gnorm2[i] = 0.f;
    if (i < NB*ND) g_monorm2[i] = 0.f;
    if (i < NB)    out[i] = wpb[0];
}

// ---------- gto: basis values + sum_g gto^2 ----------
__global__ void __launch_bounds__(256) gtoK(const float* __restrict__ dist,
                                            const int* __restrict__ qn,
                                            const int* __restrict__ ao,
                                            const float* __restrict__ zeta) {
    int b  = blockIdx.y;
    int a  = threadIdx.x & 63;
    int gl = threadIdx.x >> 6;           // 0..3
    int q  = qn[b*NA + a];
    float z = zeta[ao[b*NA + a]];
    long base = ((long)b*NG + (long)blockIdx.x*512) * NA;
    float acc = 0.f;
    for (int i = gl; i < 512; i += 4) {
        float d  = dist[base + (long)i*NA + a];
        float zd = z * d;
        float p  = (q == 0) ? 1.0f : ((q == 1) ? d : d*d);
        float v  = p * fast_expneg(zd*zd);
        g_gto[base + (long)i*NA + a] = v;
        acc = fmaf(v, v, acc);
    }
    __shared__ float s[4][64];
    s[gl][a] = acc;
    __syncthreads();
    if (threadIdx.x < 64) {
        float t = s[0][a] + s[1][a] + s[2][a] + s[3][a];
        atomicAdd(&g_gnorm2[b*NA + a], t);
    }
}

// ---------- ceff = coef/||c||_a / ||gto||_g ----------
__global__ void prepK(const int* __restrict__ ao, const float* __restrict__ coef) {
    int b = blockIdx.x;
    int d = threadIdx.x;                  // 0..127
    __shared__ float rg[64];
    __shared__ int   aos[64];
    if (d < 64) {
        aos[d] = ao[b*NA + d];
        rg[d]  = 1.f / fmaxf(sqrtf(g_gnorm2[b*NA + d]), 1e-12f);
    }
    __syncthreads();
    float cn = 0.f;
    for (int a = 0; a < NA; a++) { float c = coef[aos[a]*ND + d]; cn = fmaf(c, c, cn); }
    float rc = 1.f / fmaxf(sqrtf(cn), 1e-12f);
    for (int a = 0; a < NA; a++)
        g_ceff[(b*NA + a)*ND + d] = coef[aos[a]*ND + d] * rc * rg[a];
}

// ---------- fold layer 0 into (u, t) ----------
__global__ void utK(const float* __restrict__ wprew, const float* __restrict__ wpreb,
                    const float* __restrict__ wfw,   const float* __restrict__ wfb) {
    int e = threadIdx.x;
    float u = 0.f, t = 0.f;
    for (int d = 0; d < ND; d++) {
        float w = wfw[e*ND + d];          // layer 0, [e][d]
        u = fmaf(w, wprew[d], u);
        t = fmaf(w, wpreb[d], t);
    }
    g_u[e] = u;
    g_t[e] = t + wfb[e];
}

// ---------- transpose W1, W2 to [d][e] ----------
__global__ void transWK(const float* __restrict__ wfw) {
    float* dst = (blockIdx.x == 0) ? g_W1t : g_W2t;
    const float* src = wfw + (blockIdx.x + 1) * ND * ND;   // layers 1, 2
    for (int i = threadIdx.x; i < ND*ND; i += blockDim.x) {
        int e = i >> 7, d = i & 127;
        dst[d*ND + e] = src[i];
    }
}

// ---------- mo GEMM (packed f32x2) + column sums of squares ----------
__global__ void __launch_bounds__(256) moK() {
    extern __shared__ float sm[];
    float* gtoS   = sm;                   // 64*64
    float* ceffS  = sm + 64*64;           // 64*128
    float* colsum = ceffS + 64*128;       // 128
    int b  = blockIdx.y;
    int g0b = blockIdx.x * 64;
    int tid = threadIdx.x;
    if (tid < 128) colsum[tid] = 0.f;

    const float* cef = g_ceff + b*NA*ND;
    for (int i = tid; i < 64*128/4; i += 256)
        ((float4*)ceffS)[i] = ((const float4*)cef)[i];
    long gb = ((long)b*NG + g0b) * NA;
    for (int i = tid; i < 64*64/4; i += 256)
        ((float4*)gtoS)[i] = ((const float4*)(g_gto + gb))[i];
    __syncthreads();

    int eq8 = tid & 15;                   // 16 col groups of 8
    int gq4 = tid >> 4;                   // 16 row groups of 4
    int g0 = gq4 * 4, c0 = eq8 * 8;

    u64 acc[4][4];
    #pragma unroll
    for (int r = 0; r < 4; r++)
        #pragma unroll
        for (int jp = 0; jp < 4; jp++) acc[r][jp] = 0ull;

    gemm_core(gtoS, 64, ceffS, acc, g0, c0, NA/4);

    float cs[8];
    #pragma unroll
    for (int j = 0; j < 8; j++) cs[j] = 0.f;
    long mb = ((long)b*NG + g0b) * ND;
    #pragma unroll
    for (int r = 0; r < 4; r++) {
        float2 f0 = up2(acc[r][0]), f1 = up2(acc[r][1]);
        float2 f2 = up2(acc[r][2]), f3 = up2(acc[r][3]);
        float4 o0 = make_float4(f0.x, f0.y, f1.x, f1.y);
        float4 o1 = make_float4(f2.x, f2.y, f3.x, f3.y);
        *(float4*)&g_mo[mb + (long)(g0 + r)*ND + c0]     = o0;
        *(float4*)&g_mo[mb + (long)(g0 + r)*ND + c0 + 4] = o1;
        cs[0] = fmaf(f0.x, f0.x, cs[0]); cs[1] = fmaf(f0.y, f0.y, cs[1]);
        cs[2] = fmaf(f1.x, f1.x, cs[2]); cs[3] = fmaf(f1.y, f1.y, cs[3]);
        cs[4] = fmaf(f2.x, f2.x, cs[4]); cs[5] = fmaf(f2.y, f2.y, cs[5]);
        cs[6] = fmaf(f3.x, f3.x, cs[6]); cs[7] = fmaf(f3.y, f3.y, cs[7]);
    }
    __syncthreads();     // colsum zeroed + all smem reads done
    #pragma unroll
    for (int j = 0; j < 8; j++) atomicAdd(&colsum[c0 + j], cs[j]);
    __syncthreads();
    if (tid < 128) atomicAdd(&g_monorm2[b*ND + tid], colsum[tid]);
}

// ---------- invmo = sqrt(Ne/128)/max(||mo||,eps) ----------
__global__ void invmoK(const float* __restrict__ Ne) {
    int i = blockIdx.x * blockDim.x + threadIdx.x;
    if (i < NB*ND) {
        int b = i >> 7;
        float s = sqrtf(Ne[b] / (float)ND);
        g_invmo[i] = s / fmaxf(sqrtf(g_monorm2[i]), 1e-12f);
    }
}

// ---------- persistent fused MLP (packed f32x2 GEMMs) ----------
__global__ void __launch_bounds__(256) mlpK(const float* __restrict__ wfb,
                                            const float* __restrict__ wpw,
                                            float* __restrict__ out) {
    extern __shared__ float sm[];
    float* W1   = sm;                     // 128*128 [d][e]
    float* W2   = W1 + ND*ND;             // 128*128 [d][e]
    float* bufA = W2 + ND*ND;             // 64*128
    float* bufB = bufA + GT*ND;           // 64*132 (padded)
    float* us   = bufB + GT*BSTRIDE;
    float* ts   = us  + ND;
    float* b1s  = ts  + ND;
    float* b2s  = b1s + ND;
    float* wps  = b2s + ND;
    float* inv  = wps + ND;
    float* dens = inv + ND;               // 64
    float* red  = dens + GT;              // 8
    int tid = threadIdx.x;

    for (int i = tid; i < ND*ND; i += 256) { W1[i] = g_W1t[i]; W2[i] = g_W2t[i]; }
    if (tid < ND) {
        us[tid]  = g_u[tid];
        ts[tid]  = g_t[tid];
        b1s[tid] = wfb[ND + tid];         // layer-1 bias
        b2s[tid] = wfb[2*ND + tid];       // layer-2 bias
        wps[tid] = wpw[tid];
    }
    int eq8 = tid & 15;
    int gq4 = tid >> 4;
    int g0 = gq4 * 4, c0 = eq8 * 8;

    for (int tile = blockIdx.x; tile < NTILES; tile += gridDim.x) {
        int b   = tile >> 9;              // 512 tiles per molecule
        int gt0 = (tile & 511) * GT;
        __syncthreads();                  // buffers free from previous tile
        if (tid < ND) inv[tid] = g_invmo[b*ND + tid];

        long mbase = ((long)b*NG + gt0) * ND;
        for (int i = tid; i < GT*32; i += 256) {
            int g = i >> 5, c = i & 31;
            *(float4*)&bufB[g*BSTRIDE + 4*c] = *(const float4*)&g_mo[mbase + (long)g*ND + 4*c];
        }
        __syncthreads();

        // density per grid point (4 threads/g, d interleaved -> conflict-free)
        {
            int g = tid >> 2, l4 = tid & 3;
            float s = 0.f;
            #pragma unroll
            for (int k = 0; k < 32; k++) {
                int d = l4 + 4*k;
                float m = bufB[g*BSTRIDE + d] * inv[d];
                s = fmaf(m, m, s);
            }
            s += __shfl_xor_sync(0xffffffffu, s, 1);
            s += __shfl_xor_sync(0xffffffffu, s, 2);
            if (l4 == 0) dens[g] = s;
        }
        __syncthreads();

        // v1 = relu(density*u + t)  (layer 0+1 folded)
        for (int i = tid; i < GT*ND; i += 256) {
            int g = i >> 7, e = i & 127;
            bufA[i] = fmaxf(fmaf(dens[g], us[e], ts[e]), 0.f);
        }
        __syncthreads();

        // GEMM1: bufB = relu(bufA @ W1^T + b1)
        u64 acc[4][4];
        {
            const u64* bb = (const u64*)&b1s[c0];
            #pragma unroll
            for (int jp = 0; jp < 4; jp++) {
                u64 bv = bb[jp];
                acc[0][jp] = bv; acc[1][jp] = bv; acc[2][jp] = bv; acc[3][jp] = bv;
            }
        }
        gemm_core(bufA, ND, W1, acc, g0, c0, ND/4);
        #pragma unroll
        for (int r = 0; r < 4; r++) {
            float2 f0 = up2(acc[r][0]), f1 = up2(acc[r][1]);
            float2 f2 = up2(acc[r][2]), f3 = up2(acc[r][3]);
            float4 o0 = make_float4(fmaxf(f0.x,0.f), fmaxf(f0.y,0.f),
                                    fmaxf(f1.x,0.f), fmaxf(f1.y,0.f));
            float4 o1 = make_float4(fmaxf(f2.x,0.f), fmaxf(f2.y,0.f),
                                    fmaxf(f3.x,0.f), fmaxf(f3.y,0.f));
            *(float4*)&bufB[(g0 + r)*BSTRIDE + c0]     = o0;
            *(float4*)&bufB[(g0 + r)*BSTRIDE + c0 + 4] = o1;
        }
        __syncthreads();

        // GEMM2 + fused epilogue: relu, dot with W_prop, block reduce
        {
            const u64* bb = (const u64*)&b2s[c0];
            #pragma unroll
            for (int jp = 0; jp < 4; jp++) {
                u64 bv = bb[jp];
                acc[0][jp] = bv; acc[1][jp] = bv; acc[2][jp] = bv; acc[3][jp] = bv;
            }
        }
        gemm_core(bufB, BSTRIDE, W2, acc, g0, c0, ND/4);
        float local = 0.f;
        {
            const u64* wpp = (const u64*)&wps[c0];
            float2 w0 = up2(wpp[0]), w1 = up2(wpp[1]);
            float2 w2 = up2(wpp[2]), w3 = up2(wpp[3]);
            #pragma unroll
            for (int r = 0; r < 4; r++) {
                float2 f0 = up2(acc[r][0]), f1 = up2(acc[r][1]);
                float2 f2 = up2(acc[r][2]), f3 = up2(acc[r][3]);
                local += fmaxf(f0.x,0.f)*w0.x + fmaxf(f0.y,0.f)*w0.y
                       + fmaxf(f1.x,0.f)*w1.x + fmaxf(f1.y,0.f)*w1.y
                       + fmaxf(f2.x,0.f)*w2.x + fmaxf(f2.y,0.f)*w2.y
                       + fmaxf(f3.x,0.f)*w3.x + fmaxf(f3.y,0.f)*w3.y;
            }
        }
        #pragma unroll
        for (int off = 16; off; off >>= 1) local += __shfl_xor_sync(0xffffffffu, local, off);
        if ((tid & 31) == 0) red[tid >> 5] = local;
        __syncthreads();
        if (tid == 0) {
            float s = 0.f;
            #pragma unroll
            for (int w = 0; w < 8; w++) s += red[w];
            atomicAdd(&out[b], s);
        }
    }
}

extern "C" void kernel_launch(void* const* d_in, const int* in_sizes, int n_in,
                              void* d_out, int out_size) {
    const float* dist  = (const float*)d_in[0];
    const int*   qn    = (const int*)  d_in[1];
    const int*   ao    = (const int*)  d_in[2];
    const float* Ne    = (const float*)d_in[3];
    const float* coef  = (const float*)d_in[4];
    const float* zeta  = (const float*)d_in[5];
    const float* wprew = (const float*)d_in[6];
    const float* wpreb = (const float*)d_in[7];
    const float* wfw   = (const float*)d_in[8];
    const float* wfb   = (const float*)d_in[9];
    const float* wpw   = (const float*)d_in[10];
    const float* wpb   = (const float*)d_in[11];
    float* out = (float*)d_out;

    const int moSmem  = (64*64 + 64*128 + 128) * 4;
    const int mlpSmem = (ND*ND*2 + GT*ND + GT*BSTRIDE + ND*6 + GT + 8) * 4;
    cudaFuncSetAttribute(moK,  cudaFuncAttributeMaxDynamicSharedMemorySize, moSmem);
    cudaFuncSetAttribute(mlpK, cudaFuncAttributeMaxDynamicSharedMemorySize, mlpSmem);

    int sms = 148;
    cudaDeviceGetAttribute(&sms, cudaDevAttrMultiProcessorCount, 0);

    initK<<<1, 1024>>>(out, wpb);
    gtoK<<<dim3(NG/512, NB), 256>>>(dist, qn, ao, zeta);
    prepK<<<NB, 128>>>(ao, coef);
    utK<<<1, 128>>>(wprew, wpreb, wfw, wfb);
    transWK<<<2, 256>>>(wfw);
    moK<<<dim3(NG/64, NB), 256, moSmem>>>();
    invmoK<<<1, 1024>>>(Ne);
    mlpK<<<sms, 256, mlpSmem>>>(wfb, wpw, out);
}

// round 3
// speedup vs baseline: 1.0020x; 1.0020x over previous
#include <cuda_runtime.h>
#include <math.h>

#define NB 8
#define NG 32768
#define NA 64
#define ND 128
#define GT 64
#define NTILES (NB*(NG/GT))   // 4096
#define BSTRIDE 132

typedef unsigned long long u64;

// ---- scratch (static device allocations are allowed) ----
__device__ float g_gto[NB*NG*NA];        // 64 MB
__device__ float g_mo [NB*NG*ND];        // 128 MB
__device__ float g_gnorm2 [NB*NA];
__device__ float g_monorm2[NB*ND];
__device__ float g_ceff[NB*NA*ND];
__device__ float g_invmo[NB*ND];
__device__ float g_u[ND];
__device__ float g_t[ND];
__device__ float g_W1t[ND*ND];           // layer-1 weights, [d][e]
__device__ float g_W2t[ND*ND];           // layer-2 weights, [d][e]

// ---------- packed f32x2 helpers ----------
static __device__ __forceinline__ u64 dup2(float x) {
    u64 r; asm("mov.b64 %0, {%1, %1};" : "=l"(r) : "f"(x)); return r;
}
static __device__ __forceinline__ void ffma2(u64& acc, u64 a, u64 b) {
    asm("fma.rn.f32x2 %0, %1, %2, %0;" : "+l"(acc) : "l"(a), "l"(b));
}
static __device__ __forceinline__ float2 up2(u64 v) {
    float2 f; asm("mov.b64 {%0, %1}, %2;" : "=f"(f.x), "=f"(f.y) : "l"(v)); return f;
}

// Packed GEMM core: 4 rows (g0..g0+3) x 8 cols (c0..c0+7) per thread.
// A: [g][astride] activations (read along k), W: [k][ND] weights (cols contiguous).
// acc[r][jp] packs output cols (c0+2*jp, c0+2*jp+1).
static __device__ __forceinline__ void gemm_core(
    const float* __restrict__ A, int astride,
    const float* __restrict__ W,
    u64 acc[4][4], int g0, int c0, int K4)
{
    #pragma unroll 4
    for (int k4 = 0; k4 < K4; k4++) {
        u64 w[4][4];
        #pragma unroll
        for (int k = 0; k < 4; k++) {
            const u64* wr = (const u64*)(W + (4*k4 + k)*ND + c0);
            w[k][0] = wr[0]; w[k][1] = wr[1]; w[k][2] = wr[2]; w[k][3] = wr[3];
        }
        #pragma unroll
        for (int r = 0; r < 4; r++) {
            float4 v = *(const float4*)(A + (g0 + r)*astride + 4*k4);
            u64 d0 = dup2(v.x), d1 = dup2(v.y), d2 = dup2(v.z), d3 = dup2(v.w);
            #pragma unroll
            for (int jp = 0; jp < 4; jp++) {
                ffma2(acc[r][jp], d0, w[0][jp]);
                ffma2(acc[r][jp], d1, w[1][jp]);
                ffma2(acc[r][jp], d2, w[2][jp]);
                ffma2(acc[r][jp], d3, w[3][jp]);
            }
        }
    }
}

// ---------- fast exp(-x) via FMA-pipe poly (no MUFU) ----------
static __device__ __forceinline__ float fast_expneg(float x) {
    // 2^t with t = -x*log2(e), t clamped to [-126, 0]
    float t = fmaxf(-x * 1.4426950408889634f, -126.0f);
    float k = t + 12582912.0f;                 // round-to-nearest via magic
    int   i = __float_as_int(k);
    float n = k - 12582912.0f;
    float f = t - n;                            // [-0.5, 0.5]
    float p = fmaf(f, 1.3333558e-3f, 9.6181291e-3f);
    p = fmaf(f, p, 5.5504109e-2f);
    p = fmaf(f, p, 2.4022651e-1f);
    p = fmaf(f, p, 6.9314718e-1f);
    p = fmaf(f, p, 1.0f);
    float s = __int_as_float((i + (127 - 0x4B400000)) << 23);   // 2^n
    return p * s;
}

// ---------- init: zero accumulators, seed output with W_prop_b ----------
__global__ void initK(float* out, const float* __restrict__ wpb) {
    int i = blockIdx.x * blockDim.x + threadIdx.x;
    if (i < NB*NA) g_gnorm2[i] = 0.f;
    if (i < NB*ND) g_monorm2[i] = 0.f;
    if (i < NB)    out[i] = wpb[0];
}

// ---------- gto: basis values + sum_g gto^2 ----------
__global__ void __launch_bounds__(256) gtoK(const float* __restrict__ dist,
                                            const int* __restrict__ qn,
                                            const int* __restrict__ ao,
                                            const float* __restrict__ zeta) {
    int b  = blockIdx.y;
    int a  = threadIdx.x & 63;
    int gl = threadIdx.x >> 6;           // 0..3
    int q  = qn[b*NA + a];
    float z = zeta[ao[b*NA + a]];
    long base = ((long)b*NG + (long)blockIdx.x*512) * NA;
    float acc = 0.f;
    for (int i = gl; i < 512; i += 4) {
        float d  = dist[base + (long)i*NA + a];
        float zd = z * d;
        float p  = (q == 0) ? 1.0f : ((q == 1) ? d : d*d);
        float v  = p * fast_expneg(zd*zd);
        g_gto[base + (long)i*NA + a] = v;
        acc = fmaf(v, v, acc);
    }
    __shared__ float s[4][64];
    s[gl][a] = acc;
    __syncthreads();
    if (threadIdx.x < 64) {
        float t = s[0][a] + s[1][a] + s[2][a] + s[3][a];
        atomicAdd(&g_gnorm2[b*NA + a], t);
    }
}

// ---------- ceff = coef/||c||_a / ||gto||_g ----------
__global__ void prepK(const int* __restrict__ ao, const float* __restrict__ coef) {
    int b = blockIdx.x;
    int d = threadIdx.x;                  // 0..127
    __shared__ float rg[64];
    __shared__ int   aos[64];
    if (d < 64) {
        aos[d] = ao[b*NA + d];
        rg[d]  = 1.f / fmaxf(sqrtf(g_gnorm2[b*NA + d]), 1e-12f);
    }
    __syncthreads();
    float cn = 0.f;
    for (int a = 0; a < NA; a++) { float c = coef[aos[a]*ND + d]; cn = fmaf(c, c, cn); }
    float rc = 1.f / fmaxf(sqrtf(cn), 1e-12f);
    for (int a = 0; a < NA; a++)
        g_ceff[(b*NA + a)*ND + d] = coef[aos[a]*ND + d] * rc * rg[a];
}

// ---------- fold layer 0 into (u, t) ----------
__global__ void utK(const float* __restrict__ wprew, const float* __restrict__ wpreb,
                    const float* __restrict__ wfw,   const float* __restrict__ wfb) {
    int e = threadIdx.x;
    float u = 0.f, t = 0.f;
    for (int d = 0; d < ND; d++) {
        float w = wfw[e*ND + d];          // layer 0, [e][d]
        u = fmaf(w, wprew[d], u);
        t = fmaf(w, wpreb[d], t);
    }
    g_u[e] = u;
    g_t[e] = t + wfb[e];
}

// ---------- transpose W1, W2 to [d][e] ----------
__global__ void transWK(const float* __restrict__ wfw) {
    float* dst = (blockIdx.x == 0) ? g_W1t : g_W2t;
    const float* src = wfw + (blockIdx.x + 1) * ND * ND;   // layers 1, 2
    for (int i = threadIdx.x; i < ND*ND; i += blockDim.x) {
        int e = i >> 7, d = i & 127;
        dst[d*ND + e] = src[i];
    }
}

// ---------- mo GEMM (packed f32x2) + column sums of squares ----------
__global__ void __launch_bounds__(256) moK() {
    extern __shared__ float sm[];
    float* gtoS   = sm;                   // 64*64
    float* ceffS  = sm + 64*64;           // 64*128
    float* colsum = ceffS + 64*128;       // 128
    int b  = blockIdx.y;
    int g0b = blockIdx.x * 64;
    int tid = threadIdx.x;
    if (tid < 128) colsum[tid] = 0.f;

    const float* cef = g_ceff + b*NA*ND;
    for (int i = tid; i < 64*128/4; i += 256)
        ((float4*)ceffS)[i] = ((const float4*)cef)[i];
    long gb = ((long)b*NG + g0b) * NA;
    for (int i = tid; i < 64*64/4; i += 256)
        ((float4*)gtoS)[i] = ((const float4*)(g_gto + gb))[i];
    __syncthreads();

    int eq8 = tid & 15;                   // 16 col groups of 8
    int gq4 = tid >> 4;                   // 16 row groups of 4
    int g0 = gq4 * 4, c0 = eq8 * 8;

    u64 acc[4][4];
    #pragma unroll
    for (int r = 0; r < 4; r++)
        #pragma unroll
        for (int jp = 0; jp < 4; jp++) acc[r][jp] = 0ull;

    gemm_core(gtoS, 64, ceffS, acc, g0, c0, NA/4);

    float cs[8];
    #pragma unroll
    for (int j = 0; j < 8; j++) cs[j] = 0.f;
    long mb = ((long)b*NG + g0b) * ND;
    #pragma unroll
    for (int r = 0; r < 4; r++) {
        float2 f0 = up2(acc[r][0]), f1 = up2(acc[r][1]);
        float2 f2 = up2(acc[r][2]), f3 = up2(acc[r][3]);
        float4 o0 = make_float4(f0.x, f0.y, f1.x, f1.y);
        float4 o1 = make_float4(f2.x, f2.y, f3.x, f3.y);
        *(float4*)&g_mo[mb + (long)(g0 + r)*ND + c0]     = o0;
        *(float4*)&g_mo[mb + (long)(g0 + r)*ND + c0 + 4] = o1;
        cs[0] = fmaf(f0.x, f0.x, cs[0]); cs[1] = fmaf(f0.y, f0.y, cs[1]);
        cs[2] = fmaf(f1.x, f1.x, cs[2]); cs[3] = fmaf(f1.y, f1.y, cs[3]);
        cs[4] = fmaf(f2.x, f2.x, cs[4]); cs[5] = fmaf(f2.y, f2.y, cs[5]);
        cs[6] = fmaf(f3.x, f3.x, cs[6]); cs[7] = fmaf(f3.y, f3.y, cs[7]);
    }
    __syncthreads();     // colsum zeroed + all smem reads done
    #pragma unroll
    for (int j = 0; j < 8; j++) atomicAdd(&colsum[c0 + j], cs[j]);
    __syncthreads();
    if (tid < 128) atomicAdd(&g_monorm2[b*ND + tid], colsum[tid]);
}

// ---------- invmo = sqrt(Ne/128)/max(||mo||,eps) ----------
__global__ void invmoK(const float* __restrict__ Ne) {
    int i = blockIdx.x * blockDim.x + threadIdx.x;
    if (i < NB*ND) {
        int b = i >> 7;
        float s = sqrtf(Ne[b] / (float)ND);
        g_invmo[i] = s / fmaxf(sqrtf(g_monorm2[i]), 1e-12f);
    }
}

// ---------- persistent fused MLP (packed f32x2 GEMMs) ----------
__global__ void __launch_bounds__(256) mlpK(const float* __restrict__ wfb,
                                            const float* __restrict__ wpw,
                                            float* __restrict__ out) {
    extern __shared__ float sm[];
    float* W1   = sm;                     // 128*128 [d][e]
    float* W2   = W1 + ND*ND;             // 128*128 [d][e]
    float* bufA = W2 + ND*ND;             // 64*128
    float* bufB = bufA + GT*ND;           // 64*132 (padded)
    float* us   = bufB + GT*BSTRIDE;
    float* ts   = us  + ND;
    float* b1s  = ts  + ND;
    float* b2s  = b1s + ND;
    float* wps  = b2s + ND;
    float* inv  = wps + ND;
    float* dens = inv + ND;               // 64
    float* red  = dens + GT;              // 8
    int tid = threadIdx.x;

    for (int i = tid; i < ND*ND; i += 256) { W1[i] = g_W1t[i]; W2[i] = g_W2t[i]; }
    if (tid < ND) {
        us[tid]  = g_u[tid];
        ts[tid]  = g_t[tid];
        b1s[tid] = wfb[ND + tid];         // layer-1 bias
        b2s[tid] = wfb[2*ND + tid];       // layer-2 bias
        wps[tid] = wpw[tid];
    }
    int eq8 = tid & 15;
    int gq4 = tid >> 4;
    int g0 = gq4 * 4, c0 = eq8 * 8;

    for (int tile = blockIdx.x; tile < NTILES; tile += gridDim.x) {
        int b   = tile >> 9;              // 512 tiles per molecule
        int gt0 = (tile & 511) * GT;
        __syncthreads();                  // buffers free from previous tile
        if (tid < ND) inv[tid] = g_invmo[b*ND + tid];

        long mbase = ((long)b*NG + gt0) * ND;
        for (int i = tid; i < GT*32; i += 256) {
            int g = i >> 5, c = i & 31;
            *(float4*)&bufB[g*BSTRIDE + 4*c] = *(const float4*)&g_mo[mbase + (long)g*ND + 4*c];
        }
        __syncthreads();

        // density per grid point (4 threads/g, d interleaved -> conflict-free)
        {
            int g = tid >> 2, l4 = tid & 3;
            float s = 0.f;
            #pragma unroll
            for (int k = 0; k < 32; k++) {
                int d = l4 + 4*k;
                float m = bufB[g*BSTRIDE + d] * inv[d];
                s = fmaf(m, m, s);
            }
            s += __shfl_xor_sync(0xffffffffu, s, 1);
            s += __shfl_xor_sync(0xffffffffu, s, 2);
            if (l4 == 0) dens[g] = s;
        }
        __syncthreads();

        // v1 = relu(density*u + t)  (layer 0+1 folded)
        for (int i = tid; i < GT*ND; i += 256) {
            int g = i >> 7, e = i & 127;
            bufA[i] = fmaxf(fmaf(dens[g], us[e], ts[e]), 0.f);
        }
        __syncthreads();

        // GEMM1: bufB = relu(bufA @ W1^T + b1)
        u64 acc[4][4];
        {
            const u64* bb = (const u64*)&b1s[c0];
            #pragma unroll
            for (int jp = 0; jp < 4; jp++) {
                u64 bv = bb[jp];
                acc[0][jp] = bv; acc[1][jp] = bv; acc[2][jp] = bv; acc[3][jp] = bv;
            }
        }
        gemm_core(bufA, ND, W1, acc, g0, c0, ND/4);
        #pragma unroll
        for (int r = 0; r < 4; r++) {
            float2 f0 = up2(acc[r][0]), f1 = up2(acc[r][1]);
            float2 f2 = up2(acc[r][2]), f3 = up2(acc[r][3]);
            float4 o0 = make_float4(fmaxf(f0.x,0.f), fmaxf(f0.y,0.f),
                                    fmaxf(f1.x,0.f), fmaxf(f1.y,0.f));
            float4 o1 = make_float4(fmaxf(f2.x,0.f), fmaxf(f2.y,0.f),
                                    fmaxf(f3.x,0.f), fmaxf(f3.y,0.f));
            *(float4*)&bufB[(g0 + r)*BSTRIDE + c0]     = o0;
            *(float4*)&bufB[(g0 + r)*BSTRIDE + c0 + 4] = o1;
        }
        __syncthreads();

        // GEMM2 + fused epilogue: relu, dot with W_prop, block reduce
        {
            const u64* bb = (const u64*)&b2s[c0];
            #pragma unroll
            for (int jp = 0; jp < 4; jp++) {
                u64 bv = bb[jp];
                acc[0][jp] = bv; acc[1][jp] = bv; acc[2][jp] = bv; acc[3][jp] = bv;
            }
        }
        gemm_core(bufB, BSTRIDE, W2, acc, g0, c0, ND/4);
        float local = 0.f;
        {
            const u64* wpp = (const u64*)&wps[c0];
            float2 w0 = up2(wpp[0]), w1 = up2(wpp[1]);
            float2 w2 = up2(wpp[2]), w3 = up2(wpp[3]);
            #pragma unroll
            for (int r = 0; r < 4; r++) {
                float2 f0 = up2(acc[r][0]), f1 = up2(acc[r][1]);
                float2 f2 = up2(acc[r][2]), f3 = up2(acc[r][3]);
                local += fmaxf(f0.x,0.f)*w0.x + fmaxf(f0.y,0.f)*w0.y
                       + fmaxf(f1.x,0.f)*w1.x + fmaxf(f1.y,0.f)*w1.y
                       + fmaxf(f2.x,0.f)*w2.x + fmaxf(f2.y,0.f)*w2.y
                       + fmaxf(f3.x,0.f)*w3.x + fmaxf(f3.y,0.f)*w3.y;
            }
        }
        #pragma unroll
        for (int off = 16; off; off >>= 1) local += __shfl_xor_sync(0xffffffffu, local, off);
        if ((tid & 31) == 0) red[tid >> 5] = local;
        __syncthreads();
        if (tid == 0) {
            float s = 0.f;
            #pragma unroll
            for (int w = 0; w < 8; w++) s += red[w];
            atomicAdd(&out[b], s);
        }
    }
}

extern "C" void kernel_launch(void* const* d_in, const int* in_sizes, int n_in,
                              void* d_out, int out_size) {
    const float* dist  = (const float*)d_in[0];
    const int*   qn    = (const int*)  d_in[1];
    const int*   ao    = (const int*)  d_in[2];
    const float* Ne    = (const float*)d_in[3];
    const float* coef  = (const float*)d_in[4];
    const float* zeta  = (const float*)d_in[5];
    const float* wprew = (const float*)d_in[6];
    const float* wpreb = (const float*)d_in[7];
    const float* wfw   = (const float*)d_in[8];
    const float* wfb   = (const float*)d_in[9];
    const float* wpw   = (const float*)d_in[10];
    const float* wpb   = (const float*)d_in[11];
    float* out = (float*)d_out;

    const int moSmem  = (64*64 + 64*128 + 128) * 4;
    const int mlpSmem = (ND*ND*2 + GT*ND + GT*BSTRIDE + ND*6 + GT + 8) * 4;
    cudaFuncSetAttribute(moK,  cudaFuncAttributeMaxDynamicSharedMemorySize, moSmem);
    cudaFuncSetAttribute(mlpK, cudaFuncAttributeMaxDynamicSharedMemorySize, mlpSmem);

    int sms = 148;
    cudaDeviceGetAttribute(&sms, cudaDevAttrMultiProcessorCount, 0);

    initK<<<1, 1024>>>(out, wpb);
    gtoK<<<dim3(NG/512, NB), 256>>>(dist, qn, ao, zeta);
    prepK<<<NB, 128>>>(ao, coef);
    utK<<<1, 128>>>(wprew, wpreb, wfw, wfb);
    transWK<<<2, 256>>>(wfw);
    moK<<<dim3(NG/64, NB), 256, moSmem>>>();
    invmoK<<<1, 1024>>>(Ne);
    mlpK<<<sms, 256, mlpSmem>>>(wfb, wpw, out);
}

// round 4
// speedup vs baseline: 3.1413x; 3.1352x over previous
#include <cuda_runtime.h>
#include <math.h>

#define NB 8
#define NG 32768
#define NA 64
#define ND 128
#define GT 64
#define BSTRIDE 132
#define NT_TAB 16384

// ---- scratch (static device allocations are allowed) ----
__device__ float g_gto[NB*NG*NA];        // 64 MB
__device__ float g_mo [NB*NG*ND];        // 128 MB
__device__ float g_dens[NB*NG];          // 1 MB
__device__ float g_table[NT_TAB];
__device__ unsigned g_densmax_u;
__device__ float g_gnorm2 [NB*NA];
__device__ float g_monorm2[NB*ND];
__device__ float g_ceff[NB*NA*ND];
__device__ float g_invmo[NB*ND];
__device__ float g_u[ND];
__device__ float g_t[ND];
__device__ float g_W1t[ND*ND];           // layer-1 weights, [d][e]
__device__ float g_W2t[ND*ND];           // layer-2 weights, [d][e]

static __device__ __forceinline__ void fma4(float* acc, float v, float4 w) {
    acc[0] = fmaf(v, w.x, acc[0]);
    acc[1] = fmaf(v, w.y, acc[1]);
    acc[2] = fmaf(v, w.z, acc[2]);
    acc[3] = fmaf(v, w.w, acc[3]);
}

// ---------- init ----------
__global__ void initK(float* out, const float* __restrict__ wpb) {
    int i = blockIdx.x * blockDim.x + threadIdx.x;
    if (i < NB*NA) g_gnorm2[i] = 0.f;
    if (i < NB*ND) g_monorm2[i] = 0.f;
    if (i < NB)    out[i] = wpb[0];
    if (i == 0)    g_densmax_u = 0u;
}

// ---------- gto: basis values + sum_g gto^2 ----------
__global__ void __launch_bounds__(256) gtoK(const float* __restrict__ dist,
                                            const int* __restrict__ qn,
                                            const int* __restrict__ ao,
                                            const float* __restrict__ zeta) {
    int b  = blockIdx.y;
    int a  = threadIdx.x & 63;
    int gl = threadIdx.x >> 6;           // 0..3
    int q  = qn[b*NA + a];
    float z = zeta[ao[b*NA + a]];
    long base = ((long)b*NG + (long)blockIdx.x*512) * NA;
    float acc = 0.f;
    for (int i = gl; i < 512; i += 4) {
        float d  = dist[base + (long)i*NA + a];
        float zd = z * d;
        float p  = (q == 0) ? 1.0f : ((q == 1) ? d : d*d);
        float v  = p * __expf(-zd*zd);
        g_gto[base + (long)i*NA + a] = v;
        acc = fmaf(v, v, acc);
    }
    __shared__ float s[4][64];
    s[gl][a] = acc;
    __syncthreads();
    if (threadIdx.x < 64) {
        float t = s[0][a] + s[1][a] + s[2][a] + s[3][a];
        atomicAdd(&g_gnorm2[b*NA + a], t);
    }
}

// ---------- ceff = coef/||c||_a / ||gto||_g ----------
__global__ void prepK(const int* __restrict__ ao, const float* __restrict__ coef) {
    int b = blockIdx.x;
    int d = threadIdx.x;                  // 0..127
    __shared__ float rg[64];
    __shared__ int   aos[64];
    if (d < 64) {
        aos[d] = ao[b*NA + d];
        rg[d]  = 1.f / fmaxf(sqrtf(g_gnorm2[b*NA + d]), 1e-12f);
    }
    __syncthreads();
    float cn = 0.f;
    for (int a = 0; a < NA; a++) { float c = coef[aos[a]*ND + d]; cn = fmaf(c, c, cn); }
    float rc = 1.f / fmaxf(sqrtf(cn), 1e-12f);
    for (int a = 0; a < NA; a++)
        g_ceff[(b*NA + a)*ND + d] = coef[aos[a]*ND + d] * rc * rg[a];
}

// ---------- fold layer 0 into (u, t) ----------
__global__ void utK(const float* __restrict__ wprew, const float* __restrict__ wpreb,
                    const float* __restrict__ wfw,   const float* __restrict__ wfb) {
    int e = threadIdx.x;
    float u = 0.f, t = 0.f;
    for (int d = 0; d < ND; d++) {
        float w = wfw[e*ND + d];          // layer 0, [e][d]
        u = fmaf(w, wprew[d], u);
        t = fmaf(w, wpreb[d], t);
    }
    g_u[e] = u;
    g_t[e] = t + wfb[e];
}

// ---------- transpose W1, W2 to [d][e] ----------
__global__ void transWK(const float* __restrict__ wfw) {
    float* dst = (blockIdx.x == 0) ? g_W1t : g_W2t;
    const float* src = wfw + (blockIdx.x + 1) * ND * ND;   // layers 1, 2
    for (int i = threadIdx.x; i < ND*ND; i += blockDim.x) {
        int e = i >> 7, d = i & 127;
        dst[d*ND + e] = src[i];
    }
}

// ---------- mo GEMM + column sums of squares (scalar, R1-proven) ----------
__global__ void __launch_bounds__(256) moK() {
    extern __shared__ float sm[];
    float* gtoS   = sm;                   // 64*64
    float* ceffS  = sm + 64*64;           // 64*128
    float* colsum = ceffS + 64*128;       // 128
    int b  = blockIdx.y;
    int g0 = blockIdx.x * 64;
    int tid = threadIdx.x;
    if (tid < 128) colsum[tid] = 0.f;

    const float* cef = g_ceff + b*NA*ND;
    for (int i = tid; i < 64*128/4; i += 256)
        ((float4*)ceffS)[i] = ((const float4*)cef)[i];
    long gb = ((long)b*NG + g0) * NA;
    for (int i = tid; i < 64*64/4; i += 256)
        ((float4*)gtoS)[i] = ((const float4*)(g_gto + gb))[i];
    __syncthreads();

    int eq = tid & 31, gq = tid >> 5;
    float acc[8][4];
    #pragma unroll
    for (int r = 0; r < 8; r++) { acc[r][0]=0.f; acc[r][1]=0.f; acc[r][2]=0.f; acc[r][3]=0.f; }

    #pragma unroll 4
    for (int a4 = 0; a4 < 16; a4++) {
        float4 w[4];
        #pragma unroll
        for (int k = 0; k < 4; k++) w[k] = *(const float4*)&ceffS[(4*a4 + k)*ND + 4*eq];
        #pragma unroll
        for (int r = 0; r < 8; r++) {
            float4 v = *(const float4*)&gtoS[(gq*8 + r)*64 + 4*a4];
            fma4(acc[r], v.x, w[0]); fma4(acc[r], v.y, w[1]);
            fma4(acc[r], v.z, w[2]); fma4(acc[r], v.w, w[3]);
        }
    }

    float cs[4] = {0.f, 0.f, 0.f, 0.f};
    long mb = ((long)b*NG + g0) * ND;
    #pragma unroll
    for (int r = 0; r < 8; r++) {
        float4 o = make_float4(acc[r][0], acc[r][1], acc[r][2], acc[r][3]);
        *(float4*)&g_mo[mb + (long)(gq*8 + r)*ND + 4*eq] = o;
        #pragma unroll
        for (int j = 0; j < 4; j++) cs[j] = fmaf(acc[r][j], acc[r][j], cs[j]);
    }
    __syncthreads();
    #pragma unroll
    for (int j = 0; j < 4; j++) atomicAdd(&colsum[4*eq + j], cs[j]);
    __syncthreads();
    if (tid < 128) atomicAdd(&g_monorm2[b*ND + tid], colsum[tid]);
}

// ---------- invmo = sqrt(Ne/128)/max(||mo||,eps) ----------
__global__ void invmoK(const float* __restrict__ Ne) {
    int i = blockIdx.x * blockDim.x + threadIdx.x;
    if (i < NB*ND) {
        int b = i >> 7;
        float s = sqrtf(Ne[b] / (float)ND);
        g_invmo[i] = s / fmaxf(sqrtf(g_monorm2[i]), 1e-12f);
    }
}

// ---------- densities: dens[p] = sum_d (mo*inv)^2, plus global max ----------
__global__ void __launch_bounds__(256) densK() {
    int lane = threadIdx.x & 31;
    int wid  = (blockIdx.x * 256 + threadIdx.x) >> 5;
    const int nwarp = 512 * 8;
    float lmax = 0.f;
    for (long p = wid; p < (long)NB*NG; p += nwarp) {
        int b = (int)(p >> 15);
        float4 m = *(const float4*)(g_mo + p*ND + 4*lane);
        float4 v = *(const float4*)(g_invmo + b*ND + 4*lane);
        float x0 = m.x*v.x, x1 = m.y*v.y, x2 = m.z*v.z, x3 = m.w*v.w;
        float s = x0*x0 + x1*x1 + x2*x2 + x3*x3;
        #pragma unroll
        for (int off = 16; off; off >>= 1) s += __shfl_xor_sync(0xffffffffu, s, off);
        if (lane == 0) g_dens[p] = s;
        lmax = fmaxf(lmax, s);
    }
    if (lane == 0) atomicMax(&g_densmax_u, __float_as_uint(lmax));
}

// ---------- table: phi at NT_TAB nodes over [0, densmax] ----------
__global__ void __launch_bounds__(256) tableK(const float* __restrict__ wfb,
                                              const float* __restrict__ wpw) {
    extern __shared__ float sm[];
    float* W1   = sm;                     // 128*128 [d][e]
    float* W2   = W1 + ND*ND;             // 128*128 [d][e]
    float* bufA = W2 + ND*ND;             // 64*128
    float* bufB = bufA + GT*ND;           // 64*132
    float* us   = bufB + GT*BSTRIDE;
    float* ts   = us  + ND;
    float* b1s  = ts  + ND;
    float* b2s  = b1s + ND;
    float* wps  = b2s + ND;
    int tid = threadIdx.x;

    for (int i = tid; i < ND*ND; i += 256) { W1[i] = g_W1t[i]; W2[i] = g_W2t[i]; }
    if (tid < ND) {
        us[tid]  = g_u[tid];
        ts[tid]  = g_t[tid];
        b1s[tid] = wfb[ND + tid];
        b2s[tid] = wfb[2*ND + tid];
        wps[tid] = wpw[tid];
    }
    float h = __uint_as_float(g_densmax_u) / (float)(NT_TAB - 1);
    __syncthreads();

    int t0 = blockIdx.x * GT;
    // v1 = relu(x*u + t)
    for (int i = tid; i < GT*ND; i += 256) {
        int g = i >> 7, e = i & 127;
        float x = (float)(t0 + g) * h;
        bufA[i] = fmaxf(fmaf(x, us[e], ts[e]), 0.f);
    }
    __syncthreads();

    int eq = tid & 31, gq = tid >> 5;
    // GEMM1: bufB = relu(bufA @ W1^T + b1)
    float acc[8][4];
    {
        float4 bb = *(const float4*)&b1s[4*eq];
        #pragma unroll
        for (int r = 0; r < 8; r++) { acc[r][0]=bb.x; acc[r][1]=bb.y; acc[r][2]=bb.z; acc[r][3]=bb.w; }
    }
    #pragma unroll 4
    for (int d4 = 0; d4 < 32; d4++) {
        float4 w[4];
        #pragma unroll
        for (int k = 0; k < 4; k++) w[k] = *(const float4*)&W1[(4*d4 + k)*ND + 4*eq];
        #pragma unroll
        for (int r = 0; r < 8; r++) {
            float4 v = *(const float4*)&bufA[(gq*8 + r)*ND + 4*d4];
            fma4(acc[r], v.x, w[0]); fma4(acc[r], v.y, w[1]);
            fma4(acc[r], v.z, w[2]); fma4(acc[r], v.w, w[3]);
        }
    }
    #pragma unroll
    for (int r = 0; r < 8; r++) {
        float4 o = make_float4(fmaxf(acc[r][0],0.f), fmaxf(acc[r][1],0.f),
                               fmaxf(acc[r][2],0.f), fmaxf(acc[r][3],0.f));
        *(float4*)&bufB[(gq*8 + r)*BSTRIDE + 4*eq] = o;
    }
    __syncthreads();

    // GEMM2 + fused epilogue: relu, dot with W_prop, per-row warp reduce
    {
        float4 bb = *(const float4*)&b2s[4*eq];
        #pragma unroll
        for (int r = 0; r < 8; r++) { acc[r][0]=bb.x; acc[r][1]=bb.y; acc[r][2]=bb.z; acc[r][3]=bb.w; }
    }
    #pragma unroll 4
    for (int d4 = 0; d4 < 32; d4++) {
        float4 w[4];
        #pragma unroll
        for (int k = 0; k < 4; k++) w[k] = *(const float4*)&W2[(4*d4 + k)*ND + 4*eq];
        #pragma unroll
        for (int r = 0; r < 8; r++) {
            float4 v = *(const float4*)&bufB[(gq*8 + r)*BSTRIDE + 4*d4];
            fma4(acc[r], v.x, w[0]); fma4(acc[r], v.y, w[1]);
            fma4(acc[r], v.z, w[2]); fma4(acc[r], v.w, w[3]);
        }
    }
    float4 wp4 = *(const float4*)&wps[4*eq];
    #pragma unroll
    for (int r = 0; r < 8; r++) {
        float v = fmaxf(acc[r][0],0.f)*wp4.x + fmaxf(acc[r][1],0.f)*wp4.y
                + fmaxf(acc[r][2],0.f)*wp4.z + fmaxf(acc[r][3],0.f)*wp4.w;
        #pragma unroll
        for (int off = 16; off; off >>= 1) v += __shfl_xor_sync(0xffffffffu, v, off);
        if (eq == 0) g_table[t0 + gq*8 + r] = v;
    }
}

// ---------- final: E[b] += sum_g lerp(table, dens) ----------
__global__ void __launch_bounds__(256) sumK(float* __restrict__ out) {
    extern __shared__ float T[];          // NT_TAB + 8 (red)
    float* red = T + NT_TAB;
    int tid = threadIdx.x;
    for (int i = tid; i < NT_TAB/4; i += 256)
        ((float4*)T)[i] = ((const float4*)g_table)[i];
    __syncthreads();
    float invh = (float)(NT_TAB - 1) / __uint_as_float(g_densmax_u);
    int b = blockIdx.y;
    const int chunk = NG / 8;             // 4096
    long base = (long)b*NG + blockIdx.x*chunk;
    float acc = 0.f;
    for (int i = tid; i < chunk; i += 256) {
        float dn = g_dens[base + i];
        float t  = dn * invh;
        int ix = min((int)t, NT_TAB - 2);
        float f = t - (float)ix;
        acc += fmaf(f, T[ix+1] - T[ix], T[ix]);
    }
    #pragma unroll
    for (int off = 16; off; off >>= 1) acc += __shfl_xor_sync(0xffffffffu, acc, off);
    if ((tid & 31) == 0) red[tid >> 5] = acc;
    __syncthreads();
    if (tid == 0) {
        float s = 0.f;
        #pragma unroll
        for (int w = 0; w < 8; w++) s += red[w];
        atomicAdd(&out[b], s);
    }
}

extern "C" void kernel_launch(void* const* d_in, const int* in_sizes, int n_in,
                              void* d_out, int out_size) {
    const float* dist  = (const float*)d_in[0];
    const int*   qn    = (const int*)  d_in[1];
    const int*   ao    = (const int*)  d_in[2];
    const float* Ne    = (const float*)d_in[3];
    const float* coef  = (const float*)d_in[4];
    const float* zeta  = (const float*)d_in[5];
    const float* wprew = (const float*)d_in[6];
    const float* wpreb = (const float*)d_in[7];
    const float* wfw   = (const float*)d_in[8];
    const float* wfb   = (const float*)d_in[9];
    const float* wpw   = (const float*)d_in[10];
    const float* wpb   = (const float*)d_in[11];
    float* out = (float*)d_out;

    const int moSmem  = (64*64 + 64*128 + 128) * 4;
    const int tabSmem = (ND*ND*2 + GT*ND + GT*BSTRIDE + ND*5) * 4;
    const int sumSmem = (NT_TAB + 8) * 4;
    cudaFuncSetAttribute(moK,    cudaFuncAttributeMaxDynamicSharedMemorySize, moSmem);
    cudaFuncSetAttribute(tableK, cudaFuncAttributeMaxDynamicSharedMemorySize, tabSmem);
    cudaFuncSetAttribute(sumK,   cudaFuncAttributeMaxDynamicSharedMemorySize, sumSmem);

    initK<<<1, 1024>>>(out, wpb);
    gtoK<<<dim3(NG/512, NB), 256>>>(dist, qn, ao, zeta);
    prepK<<<NB, 128>>>(ao, coef);
    utK<<<1, 128>>>(wprew, wpreb, wfw, wfb);
    transWK<<<2, 256>>>(wfw);
    moK<<<dim3(NG/64, NB), 256, moSmem>>>();
    invmoK<<<1, 1024>>>(Ne);
    densK<<<512, 256>>>();
    tableK<<<NT_TAB/GT, 256, tabSmem>>>(wfb, wpw);
    sumK<<<dim3(8, NB), 256, sumSmem>>>(out);
}

// round 6
// speedup vs baseline: 3.4969x; 1.1132x over previous
#include <cuda_runtime.h>
#include <math.h>

#define NB 8
#define NG 32768
#define NA 64
#define ND 128
#define GT 64
#define BSTRIDE 132
#define NT_TAB 8192

// ---- scratch (static device allocations are allowed) ----
__device__ float g_G[NB*64*64];          // gto^T gto per molecule
__device__ float g_M[NB*64*64];          // C diag(inv^2) C^T per molecule
__device__ float g_dens[NB*NG];          // 1 MB
__device__ float g_table[NT_TAB];
__device__ unsigned g_densmax_u;
__device__ float g_ceff[NB*NA*ND];
__device__ float g_invmo[NB*ND];
__device__ float g_u[ND];
__device__ float g_t[ND];
__device__ float g_W1t[ND*ND];
__device__ float g_W2t[ND*ND];

static __device__ __forceinline__ void fma4(float* acc, float v, float4 w) {
    acc[0] = fmaf(v, w.x, acc[0]);
    acc[1] = fmaf(v, w.y, acc[1]);
    acc[2] = fmaf(v, w.z, acc[2]);
    acc[3] = fmaf(v, w.w, acc[3]);
}

// gto value for one element
static __device__ __forceinline__ float gto_val(float d, int q, float z) {
    float zd = z * d;
    float p  = (q == 0) ? 1.0f : ((q == 1) ? d : d*d);
    return p * __expf(-zd*zd);
}

// ---------- setup: init + fold layer0 + transpose W1/W2 + zero G ----------
__global__ void setupK(float* out, const float* __restrict__ wpb,
                       const float* __restrict__ wprew, const float* __restrict__ wpreb,
                       const float* __restrict__ wfw,   const float* __restrict__ wfb) {
    int bid = blockIdx.x, tid = threadIdx.x;
    if (bid == 0) {
        if (tid < NB) out[tid] = wpb[0];
        if (tid == 0) g_densmax_u = 0u;
    } else if (bid == 1) {
        if (tid < ND) {
            int e = tid;
            float u = 0.f, t = 0.f;
            for (int d = 0; d < ND; d++) {
                float w = wfw[e*ND + d];
                u = fmaf(w, wprew[d], u);
                t = fmaf(w, wpreb[d], t);
            }
            g_u[e] = u;
            g_t[e] = t + wfb[e];
        }
    } else if (bid <= 3) {
        float* dst = (bid == 2) ? g_W1t : g_W2t;
        const float* src = wfw + (bid - 1) * ND * ND;
        for (int i = tid; i < ND*ND; i += 256) {
            int e = i >> 7, d = i & 127;
            dst[d*ND + e] = src[i];
        }
    } else {
        int b = bid - 4;                 // 8 blocks zero G
        for (int i = tid; i < 64*64; i += 256) g_G[b*4096 + i] = 0.f;
    }
}

// ---------- pass 1: gto from dist, syrk G += gto^T gto (symmetric tiles) ----------
// blockDim 160: threads 0..135 own upper-triangular 4x4 tiles of the 16x16 tile grid
#define G_SMEM ((128*68 + 64 + 64) * 4)
__global__ void __launch_bounds__(160) gtoGK(const float* __restrict__ dist,
                                             const int* __restrict__ qn,
                                             const int* __restrict__ ao,
                                             const float* __restrict__ zeta) {
    extern __shared__ float sm[];
    float* tile = sm;                    // [128][68]
    float* zs   = sm + 128*68;           // 64
    int*   qs   = (int*)(zs + 64);       // 64
    int tid = threadIdx.x;
    int b   = blockIdx.y;

    if (tid < 64) {
        qs[tid] = qn[b*NA + tid];
        zs[tid] = zeta[ao[b*NA + tid]];
    }

    // tile (ti,tj), ti<=tj, for tid<136
    int ti = 0, tj = 0;
    {
        int t = tid;
        while (ti < 16 && t >= 16 - ti) { t -= 16 - ti; ti++; }
        tj = ti + t;
    }
    bool active = (tid < 136);

    float C[4][4];
    #pragma unroll
    for (int r = 0; r < 4; r++)
        #pragma unroll
        for (int c = 0; c < 4; c++) C[r][c] = 0.f;

    __syncthreads();

    for (int tl = blockIdx.x; tl < NG/128; tl += gridDim.x) {
        long base = ((long)b*NG + (long)tl*128) * NA;
        for (int i = tid; i < 128*16; i += 160) {
            int p = i >> 4, c = i & 15;
            float4 dv = *(const float4*)(dist + base + (long)p*NA + 4*c);
            float4 gv;
            gv.x = gto_val(dv.x, qs[4*c+0], zs[4*c+0]);
            gv.y = gto_val(dv.y, qs[4*c+1], zs[4*c+1]);
            gv.z = gto_val(dv.z, qs[4*c+2], zs[4*c+2]);
            gv.w = gto_val(dv.w, qs[4*c+3], zs[4*c+3]);
            *(float4*)&tile[p*68 + 4*c] = gv;
        }
        __syncthreads();
        if (active) {
            #pragma unroll 4
            for (int k = 0; k < 128; k++) {
                float4 ai = *(const float4*)&tile[k*68 + 4*ti];
                float4 aj = *(const float4*)&tile[k*68 + 4*tj];
                fma4(C[0], ai.x, aj); fma4(C[1], ai.y, aj);
                fma4(C[2], ai.z, aj); fma4(C[3], ai.w, aj);
            }
        }
        __syncthreads();
    }

    if (active) {
        float* Gb = g_G + b*4096;
        if (ti == tj) {
            #pragma unroll
            for (int r = 0; r < 4; r++)
                #pragma unroll
                for (int c = 0; c < 4; c++)
                    atomicAdd(&Gb[(4*ti + r)*64 + 4*tj + c], C[r][c]);
        } else {
            #pragma unroll
            for (int r = 0; r < 4; r++)
                #pragma unroll
                for (int c = 0; c < 4; c++) {
                    atomicAdd(&Gb[(4*ti + r)*64 + 4*tj + c], C[r][c]);
                    atomicAdd(&Gb[(4*tj + c)*64 + 4*ti + r], C[r][c]);
                }
        }
    }
}

// ---------- ceff = coef/||c||_a / ||gto||_g  (gnorm2 = diag G) ----------
__global__ void prepK(const int* __restrict__ ao, const float* __restrict__ coef) {
    int b = blockIdx.x;
    int d = threadIdx.x;
    __shared__ float rg[64];
    __shared__ int   aos[64];
    if (d < 64) {
        aos[d] = ao[b*NA + d];
        rg[d]  = 1.f / fmaxf(sqrtf(g_G[b*4096 + d*64 + d]), 1e-12f);
    }
    __syncthreads();
    float cn = 0.f;
    for (int a = 0; a < NA; a++) { float c = coef[aos[a]*ND + d]; cn = fmaf(c, c, cn); }
    float rc = 1.f / fmaxf(sqrtf(cn), 1e-12f);
    for (int a = 0; a < NA; a++)
        g_ceff[(b*NA + a)*ND + d] = coef[aos[a]*ND + d] * rc * rg[a];
}

// ---------- monorm2_d = c_d^T G c_d ; invmo ----------
__global__ void __launch_bounds__(128) normK(const float* __restrict__ Ne) {
    __shared__ float Gs[64*64];
    int b = blockIdx.x, d = threadIdx.x;
    for (int i = d; i < 4096; i += 128) Gs[i] = g_G[b*4096 + i];
    __syncthreads();
    float c[64];
    #pragma unroll
    for (int a = 0; a < 64; a++) c[a] = g_ceff[(b*NA + a)*ND + d];
    float m = 0.f;
    for (int i = 0; i < 64; i++) {
        const float4* row = (const float4*)&Gs[i*64];
        float yi = 0.f;
        #pragma unroll
        for (int c4 = 0; c4 < 16; c4++) {
            float4 g4 = row[c4];
            yi = fmaf(g4.x, c[4*c4+0], yi);
            yi = fmaf(g4.y, c[4*c4+1], yi);
            yi = fmaf(g4.z, c[4*c4+2], yi);
            yi = fmaf(g4.w, c[4*c4+3], yi);
        }
        m = fmaf(yi, c[i], m);
    }
    float s = sqrtf(Ne[b] / (float)ND);
    g_invmo[b*ND + d] = s / fmaxf(sqrtf(m), 1e-12f);
}

// ---------- M = C diag(inv^2) C^T ----------
#define MK_SMEM ((128*68) * 4)
__global__ void __launch_bounds__(256) MkK() {
    extern __shared__ float sT[];        // [128 d][68 pad] = ceff*inv transposed
    int b = blockIdx.x, tid = threadIdx.x;
    __shared__ float inv[128];
    if (tid < 128) inv[tid] = g_invmo[b*ND + tid];
    __syncthreads();
    for (int i = tid; i < 64*128; i += 256) {
        int a = i >> 7, d = i & 127;
        sT[d*68 + a] = g_ceff[(b*NA + a)*ND + d] * inv[d];
    }
    __syncthreads();
    int i  = tid >> 2;
    int j0 = (tid & 3) * 16;
    float acc[16];
    #pragma unroll
    for (int j = 0; j < 16; j++) acc[j] = 0.f;
    for (int d = 0; d < 128; d++) {
        float ci = sT[d*68 + i];
        const float4* row = (const float4*)&sT[d*68 + j0];
        #pragma unroll
        for (int c4 = 0; c4 < 4; c4++) {
            float4 v = row[c4];
            acc[4*c4+0] = fmaf(ci, v.x, acc[4*c4+0]);
            acc[4*c4+1] = fmaf(ci, v.y, acc[4*c4+1]);
            acc[4*c4+2] = fmaf(ci, v.z, acc[4*c4+2]);
            acc[4*c4+3] = fmaf(ci, v.w, acc[4*c4+3]);
        }
    }
    #pragma unroll
    for (int j = 0; j < 16; j++) g_M[b*4096 + i*64 + j0 + j] = acc[j];
}

// ---------- pass 2: dens_g = gto_g^T M gto_g + global max ----------
#define DQ_SMEM ((256*68 + 64*68 + 64 + 64) * 4)
__global__ void __launch_bounds__(256) densQK(const float* __restrict__ dist,
                                              const int* __restrict__ qn,
                                              const int* __restrict__ ao,
                                              const float* __restrict__ zeta) {
    extern __shared__ float sm[];
    float* gt  = sm;                     // [256][68]
    float* Msm = sm + 256*68;            // [64][68]
    float* zs  = Msm + 64*68;            // 64
    int*   qs  = (int*)(zs + 64);        // 64
    int tid = threadIdx.x;
    int b   = blockIdx.y;
    int g0  = blockIdx.x * 256;

    if (tid < 64) {
        qs[tid] = qn[b*NA + tid];
        zs[tid] = zeta[ao[b*NA + tid]];
    }
    // stage M (padded rows)
    for (int i = tid; i < 64*16; i += 256) {
        int r = i >> 4, c = i & 15;
        *(float4*)&Msm[r*68 + 4*c] = *(const float4*)&g_M[b*4096 + r*64 + 4*c];
    }
    __syncthreads();

    // stage dist -> gto
    long base = ((long)b*NG + g0) * NA;
    for (int i = tid; i < 256*16; i += 256) {
        int p = i >> 4, c = i & 15;
        float4 dv = *(const float4*)(dist + base + (long)p*NA + 4*c);
        float4 gv;
        gv.x = gto_val(dv.x, qs[4*c+0], zs[4*c+0]);
        gv.y = gto_val(dv.y, qs[4*c+1], zs[4*c+1]);
        gv.z = gto_val(dv.z, qs[4*c+2], zs[4*c+2]);
        gv.w = gto_val(dv.w, qs[4*c+3], zs[4*c+3]);
        *(float4*)&gt[p*68 + 4*c] = gv;
    }
    __syncthreads();

    // quadratic form: g in registers, M rows broadcast from smem
    float g[64];
    {
        const float4* gp = (const float4*)&gt[tid*68];
        #pragma unroll
        for (int c = 0; c < 16; c++) {
            float4 v = gp[c];
            g[4*c+0] = v.x; g[4*c+1] = v.y; g[4*c+2] = v.z; g[4*c+3] = v.w;
        }
    }
    float dens = 0.f;
    for (int i = 0; i < 64; i++) {
        const float4* mrow = (const float4*)&Msm[i*68];
        float yi = 0.f;
        #pragma unroll
        for (int c = 0; c < 16; c++) {
            float4 m = mrow[c];
            yi = fmaf(m.x, g[4*c+0], yi);
            yi = fmaf(m.y, g[4*c+1], yi);
            yi = fmaf(m.z, g[4*c+2], yi);
            yi = fmaf(m.w, g[4*c+3], yi);
        }
        dens = fmaf(yi, gt[tid*68 + i], dens);
    }
    g_dens[(long)b*NG + g0 + tid] = dens;

    float mx = dens;
    #pragma unroll
    for (int off = 16; off; off >>= 1)
        mx = fmaxf(mx, __shfl_xor_sync(0xffffffffu, mx, off));
    if ((tid & 31) == 0) atomicMax(&g_densmax_u, __float_as_uint(mx));
}

// ---------- table: phi at NT_TAB nodes over [0, densmax] ----------
__global__ void __launch_bounds__(256) tableK(const float* __restrict__ wfb,
                                              const float* __restrict__ wpw) {
    extern __shared__ float sm[];
    float* W1   = sm;
    float* W2   = W1 + ND*ND;
    float* bufA = W2 + ND*ND;
    float* bufB = bufA + GT*ND;
    float* us   = bufB + GT*BSTRIDE;
    float* ts   = us  + ND;
    float* b1s  = ts  + ND;
    float* b2s  = b1s + ND;
    float* wps  = b2s + ND;
    int tid = threadIdx.x;

    for (int i = tid; i < ND*ND; i += 256) { W1[i] = g_W1t[i]; W2[i] = g_W2t[i]; }
    if (tid < ND) {
        us[tid]  = g_u[tid];
        ts[tid]  = g_t[tid];
        b1s[tid] = wfb[ND + tid];
        b2s[tid] = wfb[2*ND + tid];
        wps[tid] = wpw[tid];
    }
    float h = __uint_as_float(g_densmax_u) / (float)(NT_TAB - 1);
    __syncthreads();

    int t0 = blockIdx.x * GT;
    for (int i = tid; i < GT*ND; i += 256) {
        int g = i >> 7, e = i & 127;
        float x = (float)(t0 + g) * h;
        bufA[i] = fmaxf(fmaf(x, us[e], ts[e]), 0.f);
    }
    __syncthreads();

    int eq = tid & 31, gq = tid >> 5;
    float acc[8][4];
    {
        float4 bb = *(const float4*)&b1s[4*eq];
        #pragma unroll
        for (int r = 0; r < 8; r++) { acc[r][0]=bb.x; acc[r][1]=bb.y; acc[r][2]=bb.z; acc[r][3]=bb.w; }
    }
    #pragma unroll 4
    for (int d4 = 0; d4 < 32; d4++) {
        float4 w[4];
        #pragma unroll
        for (int k = 0; k < 4; k++) w[k] = *(const float4*)&W1[(4*d4 + k)*ND + 4*eq];
        #pragma unroll
        for (int r = 0; r < 8; r++) {
            float4 v = *(const float4*)&bufA[(gq*8 + r)*ND + 4*d4];
            fma4(acc[r], v.x, w[0]); fma4(acc[r], v.y, w[1]);
            fma4(acc[r], v.z, w[2]); fma4(acc[r], v.w, w[3]);
        }
    }
    #pragma unroll
    for (int r = 0; r < 8; r++) {
        float4 o = make_float4(fmaxf(acc[r][0],0.f), fmaxf(acc[r][1],0.f),
                               fmaxf(acc[r][2],0.f), fmaxf(acc[r][3],0.f));
        *(float4*)&bufB[(gq*8 + r)*BSTRIDE + 4*eq] = o;
    }
    __syncthreads();

    {
        float4 bb = *(const float4*)&b2s[4*eq];
        #pragma unroll
        for (int r = 0; r < 8; r++) { acc[r][0]=bb.x; acc[r][1]=bb.y; acc[r][2]=bb.z; acc[r][3]=bb.w; }
    }
    #pragma unroll 4
    for (int d4 = 0; d4 < 32; d4++) {
        float4 w[4];
        #pragma unroll
        for (int k = 0; k < 4; k++) w[k] = *(const float4*)&W2[(4*d4 + k)*ND + 4*eq];
        #pragma unroll
        for (int r = 0; r < 8; r++) {
            float4 v = *(const float4*)&bufB[(gq*8 + r)*BSTRIDE + 4*d4];
            fma4(acc[r], v.x, w[0]); fma4(acc[r], v.y, w[1]);
            fma4(acc[r], v.z, w[2]); fma4(acc[r], v.w, w[3]);
        }
    }
    float4 wp4 = *(const float4*)&wps[4*eq];
    #pragma unroll
    for (int r = 0; r < 8; r++) {
        float v = fmaxf(acc[r][0],0.f)*wp4.x + fmaxf(acc[r][1],0.f)*wp4.y
                + fmaxf(acc[r][2],0.f)*wp4.z + fmaxf(acc[r][3],0.f)*wp4.w;
        #pragma unroll
        for (int off = 16; off; off >>= 1) v += __shfl_xor_sync(0xffffffffu, v, off);
        if (eq == 0) g_table[t0 + gq*8 + r] = v;
    }
}

// ---------- final: E[b] += sum_g lerp(table, dens) ----------
__global__ void __launch_bounds__(256) sumK(float* __restrict__ out) {
    extern __shared__ float T[];
    float* red = T + NT_TAB;
    int tid = threadIdx.x;
    for (int i = tid; i < NT_TAB/4; i += 256)
        ((float4*)T)[i] = ((const float4*)g_table)[i];
    __syncthreads();
    float invh = (float)(NT_TAB - 1) / __uint_as_float(g_densmax_u);
    int b = blockIdx.y;
    const int chunk = NG / 8;
    long base = (long)b*NG + blockIdx.x*chunk;
    float acc = 0.f;
    for (int i = tid; i < chunk; i += 256) {
        float dn = g_dens[base + i];
        float t  = dn * invh;
        int ix = min((int)t, NT_TAB - 2);
        float f = t - (float)ix;
        acc += fmaf(f, T[ix+1] - T[ix], T[ix]);
    }
    #pragma unroll
    for (int off = 16; off; off >>= 1) acc += __shfl_xor_sync(0xffffffffu, acc, off);
    if ((tid & 31) == 0) red[tid >> 5] = acc;
    __syncthreads();
    if (tid == 0) {
        float s = 0.f;
        #pragma unroll
        for (int w = 0; w < 8; w++) s += red[w];
        atomicAdd(&out[b], s);
    }
}

extern "C" void kernel_launch(void* const* d_in, const int* in_sizes, int n_in,
                              void* d_out, int out_size) {
    const float* dist  = (const float*)d_in[0];
    const int*   qn    = (const int*)  d_in[1];
    const int*   ao    = (const int*)  d_in[2];
    const float* Ne    = (const float*)d_in[3];
    const float* coef  = (const float*)d_in[4];
    const float* zeta  = (const float*)d_in[5];
    const float* wprew = (const float*)d_in[6];
    const float* wpreb = (const float*)d_in[7];
    const float* wfw   = (const float*)d_in[8];
    const float* wfb   = (const float*)d_in[9];
    const float* wpw   = (const float*)d_in[10];
    const float* wpb   = (const float*)d_in[11];
    float* out = (float*)d_out;

    const int tabSmem = (ND*ND*2 + GT*ND + GT*BSTRIDE + ND*5) * 4;
    const int sumSmem = (NT_TAB + 8) * 4;
    cudaFuncSetAttribute(gtoGK,  cudaFuncAttributeMaxDynamicSharedMemorySize, G_SMEM);
    cudaFuncSetAttribute(MkK,    cudaFuncAttributeMaxDynamicSharedMemorySize, MK_SMEM);
    cudaFuncSetAttribute(densQK, cudaFuncAttributeMaxDynamicSharedMemorySize, DQ_SMEM);
    cudaFuncSetAttribute(tableK, cudaFuncAttributeMaxDynamicSharedMemorySize, tabSmem);
    cudaFuncSetAttribute(sumK,   cudaFuncAttributeMaxDynamicSharedMemorySize, sumSmem);

    setupK<<<12, 256>>>(out, wpb, wprew, wpreb, wfw, wfb);
    gtoGK<<<dim3(74, NB), 160, G_SMEM>>>(dist, qn, ao, zeta);
    prepK<<<NB, 128>>>(ao, coef);
    normK<<<NB, 128>>>(Ne);
    MkK<<<NB, 256, MK_SMEM>>>();
    densQK<<<dim3(NG/256, NB), 256, DQ_SMEM>>>(dist, qn, ao, zeta);
    tableK<<<NT_TAB/GT, 256, tabSmem>>>(wfb, wpw);
    sumK<<<dim3(8, NB), 256, sumSmem>>>(out);
}

// round 7
// speedup vs baseline: 3.8267x; 1.0943x over previous
#include <cuda_runtime.h>
#include <math.h>

#define NB 8
#define NG 32768
#define NA 64
#define ND 128
#define GT 64
#define BSTRIDE 132
#define NT_TAB 8192
#define NTILE_SYM 136      // upper-triangular 4x4 tiles of 64x64

// ---- scratch (static device allocations are allowed) ----
__device__ float g_G[NB*64*64];            // gto^T gto per molecule
__device__ float g_Mpk[NB*NTILE_SYM*16];   // packed symmetric M (off-diag doubled)
__device__ float g_dens[NB*NG];
__device__ float g_table[NT_TAB];
__device__ unsigned g_densmax_u;
__device__ float g_u[ND];
__device__ float g_t[ND];
__device__ float g_W1t[ND*ND];
__device__ float g_W2t[ND*ND];

static __device__ __forceinline__ void fma4(float* acc, float v, float4 w) {
    acc[0] = fmaf(v, w.x, acc[0]);
    acc[1] = fmaf(v, w.y, acc[1]);
    acc[2] = fmaf(v, w.z, acc[2]);
    acc[3] = fmaf(v, w.w, acc[3]);
}

static __device__ __forceinline__ float gto_val(float d, int q, float z) {
    float zd = z * d;
    float p  = (q == 0) ? 1.0f : ((q == 1) ? d : d*d);
    return p * __expf(-zd*zd);
}

// ---------- setup: init + fold layer0 + transpose W1/W2 + zero G ----------
__global__ void setupK(float* out, const float* __restrict__ wpb,
                       const float* __restrict__ wprew, const float* __restrict__ wpreb,
                       const float* __restrict__ wfw,   const float* __restrict__ wfb) {
    int bid = blockIdx.x, tid = threadIdx.x;
    if (bid == 0) {
        if (tid < NB) out[tid] = wpb[0];
        if (tid == 0) g_densmax_u = 0u;
    } else if (bid == 1) {
        if (tid < ND) {
            int e = tid;
            float u = 0.f, t = 0.f;
            for (int d = 0; d < ND; d++) {
                float w = wfw[e*ND + d];
                u = fmaf(w, wprew[d], u);
                t = fmaf(w, wpreb[d], t);
            }
            g_u[e] = u;
            g_t[e] = t + wfb[e];
        }
    } else if (bid <= 3) {
        float* dst = (bid == 2) ? g_W1t : g_W2t;
        const float* src = wfw + (bid - 1) * ND * ND;
        for (int i = tid; i < ND*ND; i += 256) {
            int e = i >> 7, d = i & 127;
            dst[d*ND + e] = src[i];
        }
    } else {
        int b = bid - 4;
        for (int i = tid; i < 64*64; i += 256) g_G[b*4096 + i] = 0.f;
    }
}

// ---------- pass 1: gto from dist, syrk G += gto^T gto (symmetric tiles) ----------
#define G_SMEM ((128*68 + 64 + 64) * 4)
__global__ void __launch_bounds__(160) gtoGK(const float* __restrict__ dist,
                                             const int* __restrict__ qn,
                                             const int* __restrict__ ao,
                                             const float* __restrict__ zeta) {
    extern __shared__ float sm[];
    float* tile = sm;                    // [128][68]
    float* zs   = sm + 128*68;
    int*   qs   = (int*)(zs + 64);
    int tid = threadIdx.x;
    int b   = blockIdx.y;

    if (tid < 64) {
        qs[tid] = qn[b*NA + tid];
        zs[tid] = zeta[ao[b*NA + tid]];
    }

    int ti = 0, tj = 0;
    {
        int t = tid;
        while (ti < 16 && t >= 16 - ti) { t -= 16 - ti; ti++; }
        tj = ti + t;
    }
    bool active = (tid < 136);

    float C[4][4];
    #pragma unroll
    for (int r = 0; r < 4; r++)
        #pragma unroll
        for (int c = 0; c < 4; c++) C[r][c] = 0.f;

    __syncthreads();

    for (int tl = blockIdx.x; tl < NG/128; tl += gridDim.x) {
        long base = ((long)b*NG + (long)tl*128) * NA;
        for (int i = tid; i < 128*16; i += 160) {
            int p = i >> 4, c = i & 15;
            float4 dv = *(const float4*)(dist + base + (long)p*NA + 4*c);
            float4 gv;
            gv.x = gto_val(dv.x, qs[4*c+0], zs[4*c+0]);
            gv.y = gto_val(dv.y, qs[4*c+1], zs[4*c+1]);
            gv.z = gto_val(dv.z, qs[4*c+2], zs[4*c+2]);
            gv.w = gto_val(dv.w, qs[4*c+3], zs[4*c+3]);
            *(float4*)&tile[p*68 + 4*c] = gv;
        }
        __syncthreads();
        if (active) {
            #pragma unroll 4
            for (int k = 0; k < 128; k++) {
                float4 ai = *(const float4*)&tile[k*68 + 4*ti];
                float4 aj = *(const float4*)&tile[k*68 + 4*tj];
                fma4(C[0], ai.x, aj); fma4(C[1], ai.y, aj);
                fma4(C[2], ai.z, aj); fma4(C[3], ai.w, aj);
            }
        }
        __syncthreads();
    }

    if (active) {
        float* Gb = g_G + b*4096;
        if (ti == tj) {
            #pragma unroll
            for (int r = 0; r < 4; r++)
                #pragma unroll
                for (int c = 0; c < 4; c++)
                    atomicAdd(&Gb[(4*ti + r)*64 + 4*tj + c], C[r][c]);
        } else {
            #pragma unroll
            for (int r = 0; r < 4; r++)
                #pragma unroll
                for (int c = 0; c < 4; c++) {
                    atomicAdd(&Gb[(4*ti + r)*64 + 4*tj + c], C[r][c]);
                    atomicAdd(&Gb[(4*tj + c)*64 + 4*ti + r], C[r][c]);
                }
        }
    }
}

// ---------- fused prep: ceff -> monorm -> packed M, all in smem ----------
#define PF_SMEM ((4096 + 8448 + 64 + 128 + 128 + 256) * 4 + 64*4)
__global__ void __launch_bounds__(256) prepFK(const int* __restrict__ ao,
                                              const float* __restrict__ coef,
                                              const float* __restrict__ Ne) {
    extern __shared__ float sm[];
    float* Gs    = sm;                    // 4096
    float* ceffS = Gs + 4096;             // 64*132 = 8448, [a*132+d]
    float* rg    = ceffS + 8448;          // 64
    float* rc    = rg + 64;               // 128
    float* inv   = rc + 128;              // 128
    float* mpart = inv + 128;             // 256 [h*128+d]
    int*   aos   = (int*)(mpart + 256);   // 64
    int b = blockIdx.x, tid = threadIdx.x;

    // P0: load G, aos
    for (int i = tid; i < 4096; i += 256) Gs[i] = g_G[b*4096 + i];
    if (tid < 64) aos[tid] = ao[b*NA + tid];
    __syncthreads();
    if (tid < 64) rg[tid] = 1.f / fmaxf(sqrtf(Gs[tid*64 + tid]), 1e-12f);

    // P1: stage raw coef
    for (int i = tid; i < 64*128; i += 256) {
        int a = i >> 7, d = i & 127;
        ceffS[a*132 + d] = coef[aos[a]*ND + d];
    }
    __syncthreads();

    // P2: rc over AO axis
    if (tid < 128) {
        float cn = 0.f;
        #pragma unroll 8
        for (int a = 0; a < 64; a++) { float c = ceffS[a*132 + tid]; cn = fmaf(c, c, cn); }
        rc[tid] = 1.f / fmaxf(sqrtf(cn), 1e-12f);
    }
    __syncthreads();
    // P2b: ceff = coef * rc * rg
    for (int i = tid; i < 64*128; i += 256) {
        int a = i >> 7, d = i & 127;
        ceffS[a*132 + d] *= rc[d] * rg[a];
    }
    __syncthreads();

    // P3: monorm2_d = c_d^T G c_d, i-range split over 2 halves, 4 acc chains
    {
        int d = tid & 127, h = tid >> 7;
        float c[64];
        #pragma unroll
        for (int a = 0; a < 64; a++) c[a] = ceffS[a*132 + d];
        float m = 0.f;
        int i0 = 32*h;
        for (int i = i0; i < i0 + 32; i++) {
            const float4* row = (const float4*)&Gs[i*64];
            float y0 = 0.f, y1 = 0.f, y2 = 0.f, y3 = 0.f;
            #pragma unroll
            for (int k = 0; k < 4; k++) {
                float4 ga = row[k],     gb = row[k+4];
                float4 gc = row[k+8],   gd = row[k+12];
                y0 = fmaf(ga.x, c[4*k+0],  y0); y0 = fmaf(ga.y, c[4*k+1],  y0);
                y0 = fmaf(ga.z, c[4*k+2],  y0); y0 = fmaf(ga.w, c[4*k+3],  y0);
                y1 = fmaf(gb.x, c[16+4*k+0], y1); y1 = fmaf(gb.y, c[16+4*k+1], y1);
                y1 = fmaf(gb.z, c[16+4*k+2], y1); y1 = fmaf(gb.w, c[16+4*k+3], y1);
                y2 = fmaf(gc.x, c[32+4*k+0], y2); y2 = fmaf(gc.y, c[32+4*k+1], y2);
                y2 = fmaf(gc.z, c[32+4*k+2], y2); y2 = fmaf(gc.w, c[32+4*k+3], y2);
                y3 = fmaf(gd.x, c[48+4*k+0], y3); y3 = fmaf(gd.y, c[48+4*k+1], y3);
                y3 = fmaf(gd.z, c[48+4*k+2], y3); y3 = fmaf(gd.w, c[48+4*k+3], y3);
            }
            m = fmaf(y0 + y1 + y2 + y3, c[i], m);
        }
        mpart[h*128 + d] = m;
    }
    __syncthreads();
    if (tid < 128) {
        float m = mpart[tid] + mpart[128 + tid];
        float s2 = Ne[b] / (float)ND;                 // inv^2 = s2 / max(m, eps^2)
        inv[tid] = sqrtf(s2 / fmaxf(m, 1e-24f));
    }
    __syncthreads();
    // P3b: scale ceff by inv (so M = chat chat^T)
    for (int i = tid; i < 64*128; i += 256) {
        int a = i >> 7, d = i & 127;
        ceffS[a*132 + d] *= inv[d];
    }
    __syncthreads();

    // P4: packed symmetric M
    if (tid < NTILE_SYM) {
        int ti = 0, tj = 0;
        {
            int t = tid;
            while (ti < 16 && t >= 16 - ti) { t -= 16 - ti; ti++; }
            tj = ti + t;
        }
        float acc[4][4];
        #pragma unroll
        for (int r = 0; r < 4; r++)
            #pragma unroll
            for (int c = 0; c < 4; c++) acc[r][c] = 0.f;
        for (int d = 0; d < 128; d++) {
            float ci[4], cj[4];
            #pragma unroll
            for (int r = 0; r < 4; r++) ci[r] = ceffS[(4*ti + r)*132 + d];
            #pragma unroll
            for (int c = 0; c < 4; c++) cj[c] = ceffS[(4*tj + c)*132 + d];
            #pragma unroll
            for (int r = 0; r < 4; r++)
                #pragma unroll
                for (int c = 0; c < 4; c++) acc[r][c] = fmaf(ci[r], cj[c], acc[r][c]);
        }
        float sc = (ti == tj) ? 1.0f : 2.0f;
        float* dst = g_Mpk + b*NTILE_SYM*16 + tid*16;
        #pragma unroll
        for (int r = 0; r < 4; r++)
            #pragma unroll
            for (int c = 0; c < 4; c++) dst[r*4 + c] = acc[r][c] * sc;
    }
}

// ---------- pass 2: dens_g = gto^T M gto (packed symmetric) + global max ----------
#define DQ_SMEM ((256*68 + NTILE_SYM*16 + 64 + 64) * 4)
__global__ void __launch_bounds__(256) densQK(const float* __restrict__ dist,
                                              const int* __restrict__ qn,
                                              const int* __restrict__ ao,
                                              const float* __restrict__ zeta) {
    extern __shared__ float sm[];
    float* gt = sm;                        // [256][68]
    float* Mp = gt + 256*68;               // 2176
    float* zs = Mp + NTILE_SYM*16;         // 64
    int*   qs = (int*)(zs + 64);           // 64
    int tid = threadIdx.x;
    int b   = blockIdx.y;
    int g0  = blockIdx.x * 256;

    if (tid < 64) {
        qs[tid] = qn[b*NA + tid];
        zs[tid] = zeta[ao[b*NA + tid]];
    }
    for (int i = tid; i < NTILE_SYM*16; i += 256) Mp[i] = g_Mpk[b*NTILE_SYM*16 + i];
    __syncthreads();

    long base = ((long)b*NG + g0) * NA;
    for (int i = tid; i < 256*16; i += 256) {
        int p = i >> 4, c = i & 15;
        float4 dv = *(const float4*)(dist + base + (long)p*NA + 4*c);
        float4 gv;
        gv.x = gto_val(dv.x, qs[4*c+0], zs[4*c+0]);
        gv.y = gto_val(dv.y, qs[4*c+1], zs[4*c+1]);
        gv.z = gto_val(dv.z, qs[4*c+2], zs[4*c+2]);
        gv.w = gto_val(dv.w, qs[4*c+3], zs[4*c+3]);
        *(float4*)&gt[p*68 + 4*c] = gv;
    }
    __syncthreads();

    const float*  gtp = gt + tid*68;
    const float4* Mt  = (const float4*)Mp;
    float dens = 0.f;
    int t = 0;
    for (int ti = 0; ti < 16; ti++) {
        float4 gi = *(const float4*)(gtp + 4*ti);
        float y0 = 0.f, y1 = 0.f, y2 = 0.f, y3 = 0.f;
        for (int tj = ti; tj < 16; tj++, t++) {
            float4 gj = *(const float4*)(gtp + 4*tj);
            float4 m0 = Mt[4*t+0], m1 = Mt[4*t+1], m2 = Mt[4*t+2], m3 = Mt[4*t+3];
            y0 = fmaf(m0.x, gj.x, y0); y0 = fmaf(m0.y, gj.y, y0);
            y0 = fmaf(m0.z, gj.z, y0); y0 = fmaf(m0.w, gj.w, y0);
            y1 = fmaf(m1.x, gj.x, y1); y1 = fmaf(m1.y, gj.y, y1);
            y1 = fmaf(m1.z, gj.z, y1); y1 = fmaf(m1.w, gj.w, y1);
            y2 = fmaf(m2.x, gj.x, y2); y2 = fmaf(m2.y, gj.y, y2);
            y2 = fmaf(m2.z, gj.z, y2); y2 = fmaf(m2.w, gj.w, y2);
            y3 = fmaf(m3.x, gj.x, y3); y3 = fmaf(m3.y, gj.y, y3);
            y3 = fmaf(m3.z, gj.z, y3); y3 = fmaf(m3.w, gj.w, y3);
        }
        float s = gi.x*y0 + gi.y*y1;
        s = fmaf(gi.z, y2, s);
        s = fmaf(gi.w, y3, s);
        dens += s;
    }
    g_dens[(long)b*NG + g0 + tid] = dens;

    float mx = dens;
    #pragma unroll
    for (int off = 16; off; off >>= 1)
        mx = fmaxf(mx, __shfl_xor_sync(0xffffffffu, mx, off));
    if ((tid & 31) == 0) atomicMax(&g_densmax_u, __float_as_uint(mx));
}

// ---------- table: phi at NT_TAB nodes over [0, densmax] ----------
__global__ void __launch_bounds__(256) tableK(const float* __restrict__ wfb,
                                              const float* __restrict__ wpw) {
    extern __shared__ float sm[];
    float* W1   = sm;
    float* W2   = W1 + ND*ND;
    float* bufA = W2 + ND*ND;
    float* bufB = bufA + GT*ND;
    float* us   = bufB + GT*BSTRIDE;
    float* ts   = us  + ND;
    float* b1s  = ts  + ND;
    float* b2s  = b1s + ND;
    float* wps  = b2s + ND;
    int tid = threadIdx.x;

    for (int i = tid; i < ND*ND; i += 256) { W1[i] = g_W1t[i]; W2[i] = g_W2t[i]; }
    if (tid < ND) {
        us[tid]  = g_u[tid];
        ts[tid]  = g_t[tid];
        b1s[tid] = wfb[ND + tid];
        b2s[tid] = wfb[2*ND + tid];
        wps[tid] = wpw[tid];
    }
    float h = __uint_as_float(g_densmax_u) / (float)(NT_TAB - 1);
    __syncthreads();

    int t0 = blockIdx.x * GT;
    for (int i = tid; i < GT*ND; i += 256) {
        int g = i >> 7, e = i & 127;
        float x = (float)(t0 + g) * h;
        bufA[i] = fmaxf(fmaf(x, us[e], ts[e]), 0.f);
    }
    __syncthreads();

    int eq = tid & 31, gq = tid >> 5;
    float acc[8][4];
    {
        float4 bb = *(const float4*)&b1s[4*eq];
        #pragma unroll
        for (int r = 0; r < 8; r++) { acc[r][0]=bb.x; acc[r][1]=bb.y; acc[r][2]=bb.z; acc[r][3]=bb.w; }
    }
    #pragma unroll 4
    for (int d4 = 0; d4 < 32; d4++) {
        float4 w[4];
        #pragma unroll
        for (int k = 0; k < 4; k++) w[k] = *(const float4*)&W1[(4*d4 + k)*ND + 4*eq];
        #pragma unroll
        for (int r = 0; r < 8; r++) {
            float4 v = *(const float4*)&bufA[(gq*8 + r)*ND + 4*d4];
            fma4(acc[r], v.x, w[0]); fma4(acc[r], v.y, w[1]);
            fma4(acc[r], v.z, w[2]); fma4(acc[r], v.w, w[3]);
        }
    }
    #pragma unroll
    for (int r = 0; r < 8; r++) {
        float4 o = make_float4(fmaxf(acc[r][0],0.f), fmaxf(acc[r][1],0.f),
                               fmaxf(acc[r][2],0.f), fmaxf(acc[r][3],0.f));
        *(float4*)&bufB[(gq*8 + r)*BSTRIDE + 4*eq] = o;
    }
    __syncthreads();

    {
        float4 bb = *(const float4*)&b2s[4*eq];
        #pragma unroll
        for (int r = 0; r < 8; r++) { acc[r][0]=bb.x; acc[r][1]=bb.y; acc[r][2]=bb.z; acc[r][3]=bb.w; }
    }
    #pragma unroll 4
    for (int d4 = 0; d4 < 32; d4++) {
        float4 w[4];
        #pragma unroll
        for (int k = 0; k < 4; k++) w[k] = *(const float4*)&W2[(4*d4 + k)*ND + 4*eq];
        #pragma unroll
        for (int r = 0; r < 8; r++) {
            float4 v = *(const float4*)&bufB[(gq*8 + r)*BSTRIDE + 4*d4];
            fma4(acc[r], v.x, w[0]); fma4(acc[r], v.y, w[1]);
            fma4(acc[r], v.z, w[2]); fma4(acc[r], v.w, w[3]);
        }
    }
    float4 wp4 = *(const float4*)&wps[4*eq];
    #pragma unroll
    for (int r = 0; r < 8; r++) {
        float v = fmaxf(acc[r][0],0.f)*wp4.x + fmaxf(acc[r][1],0.f)*wp4.y
                + fmaxf(acc[r][2],0.f)*wp4.z + fmaxf(acc[r][3],0.f)*wp4.w;
        #pragma unroll
        for (int off = 16; off; off >>= 1) v += __shfl_xor_sync(0xffffffffu, v, off);
        if (eq == 0) g_table[t0 + gq*8 + r] = v;
    }
}

// ---------- final: E[b] += sum_g lerp(table, dens) ----------
__global__ void __launch_bounds__(256) sumK(float* __restrict__ out) {
    extern __shared__ float T[];
    float* red = T + NT_TAB;
    int tid = threadIdx.x;
    for (int i = tid; i < NT_TAB/4; i += 256)
        ((float4*)T)[i] = ((const float4*)g_table)[i];
    __syncthreads();
    float invh = (float)(NT_TAB - 1) / __uint_as_float(g_densmax_u);
    int b = blockIdx.y;
    const int chunk = NG / 8;
    long base = (long)b*NG + blockIdx.x*chunk;
    float acc = 0.f;
    for (int i = tid; i < chunk; i += 256) {
        float dn = g_dens[base + i];
        float t  = dn * invh;
        int ix = min((int)t, NT_TAB - 2);
        float f = t - (float)ix;
        acc += fmaf(f, T[ix+1] - T[ix], T[ix]);
    }
    #pragma unroll
    for (int off = 16; off; off >>= 1) acc += __shfl_xor_sync(0xffffffffu, acc, off);
    if ((tid & 31) == 0) red[tid >> 5] = acc;
    __syncthreads();
    if (tid == 0) {
        float s = 0.f;
        #pragma unroll
        for (int w = 0; w < 8; w++) s += red[w];
        atomicAdd(&out[b], s);
    }
}

extern "C" void kernel_launch(void* const* d_in, const int* in_sizes, int n_in,
                              void* d_out, int out_size) {
    const float* dist  = (const float*)d_in[0];
    const int*   qn    = (const int*)  d_in[1];
    const int*   ao    = (const int*)  d_in[2];
    const float* Ne    = (const float*)d_in[3];
    const float* coef  = (const float*)d_in[4];
    const float* zeta  = (const float*)d_in[5];
    const float* wprew = (const float*)d_in[6];
    const float* wpreb = (const float*)d_in[7];
    const float* wfw   = (const float*)d_in[8];
    const float* wfb   = (const float*)d_in[9];
    const float* wpw   = (const float*)d_in[10];
    const float* wpb   = (const float*)d_in[11];
    float* out = (float*)d_out;

    const int tabSmem = (ND*ND*2 + GT*ND + GT*BSTRIDE + ND*5) * 4;
    const int sumSmem = (NT_TAB + 8) * 4;
    cudaFuncSetAttribute(gtoGK,  cudaFuncAttributeMaxDynamicSharedMemorySize, G_SMEM);
    cudaFuncSetAttribute(prepFK, cudaFuncAttributeMaxDynamicSharedMemorySize, PF_SMEM);
    cudaFuncSetAttribute(densQK, cudaFuncAttributeMaxDynamicSharedMemorySize, DQ_SMEM);
    cudaFuncSetAttribute(tableK, cudaFuncAttributeMaxDynamicSharedMemorySize, tabSmem);
    cudaFuncSetAttribute(sumK,   cudaFuncAttributeMaxDynamicSharedMemorySize, sumSmem);

    setupK<<<12, 256>>>(out, wpb, wprew, wpreb, wfw, wfb);
    gtoGK<<<dim3(74, NB), 160, G_SMEM>>>(dist, qn, ao, zeta);
    prepFK<<<NB, 256, PF_SMEM>>>(ao, coef, Ne);
    densQK<<<dim3(NG/256, NB), 256, DQ_SMEM>>>(dist, qn, ao, zeta);
    tableK<<<NT_TAB/GT, 256, tabSmem>>>(wfb, wpw);
    sumK<<<dim3(8, NB), 256, sumSmem>>>(out);
}

// round 8
// speedup vs baseline: 4.1634x; 1.0880x over previous
#include <cuda_runtime.h>
#include <math.h>

#define NB 8
#define NG 32768
#define NA 64
#define ND 128
#define GT 64
#define BSTRIDE 132
#define NT_TAB 8192
#define NTILE_SYM 136      // upper-triangular 4x4 tiles of 64x64
#define DQP 128            // points per densQK block

// ---- scratch (static device allocations are allowed) ----
__device__ float g_G[NB*64*64];            // gto^T gto per molecule
__device__ float g_Mpk[NB*NTILE_SYM*16];   // packed symmetric M (off-diag doubled)
__device__ float g_dens[NB*NG];
__device__ float g_table[NT_TAB];
__device__ unsigned g_densmax_u;
__device__ float g_u[ND];
__device__ float g_t[ND];
__device__ float g_W1t[ND*ND];
__device__ float g_W2t[ND*ND];

static __device__ __forceinline__ void fma4(float* acc, float v, float4 w) {
    acc[0] = fmaf(v, w.x, acc[0]);
    acc[1] = fmaf(v, w.y, acc[1]);
    acc[2] = fmaf(v, w.z, acc[2]);
    acc[3] = fmaf(v, w.w, acc[3]);
}

static __device__ __forceinline__ float gto_val(float d, int q, float z) {
    float zd = z * d;
    float p  = (q == 0) ? 1.0f : ((q == 1) ? d : d*d);
    return p * __expf(-zd*zd);
}

// ---------- setup: init + fold layer0 + transpose W1/W2 + zero G ----------
__global__ void setupK(float* out, const float* __restrict__ wpb,
                       const float* __restrict__ wprew, const float* __restrict__ wpreb,
                       const float* __restrict__ wfw,   const float* __restrict__ wfb) {
    int bid = blockIdx.x, tid = threadIdx.x;
    if (bid == 0) {
        if (tid < NB) out[tid] = wpb[0];
        if (tid == 0) g_densmax_u = 0u;
    } else if (bid == 1) {
        if (tid < ND) {
            int e = tid;
            float u = 0.f, t = 0.f;
            for (int d = 0; d < ND; d++) {
                float w = wfw[e*ND + d];
                u = fmaf(w, wprew[d], u);
                t = fmaf(w, wpreb[d], t);
            }
            g_u[e] = u;
            g_t[e] = t + wfb[e];
        }
    } else if (bid <= 3) {
        float* dst = (bid == 2) ? g_W1t : g_W2t;
        const float* src = wfw + (bid - 1) * ND * ND;
        for (int i = tid; i < ND*ND; i += 256) {
            int e = i >> 7, d = i & 127;
            dst[d*ND + e] = src[i];
        }
    } else {
        int b = bid - 4;
        for (int i = tid; i < 64*64; i += 256) g_G[b*4096 + i] = 0.f;
    }
}

// ---------- pass 1: gto from dist, syrk G += gto^T gto (symmetric tiles) ----------
#define G_SMEM ((128*68 + 64 + 64) * 4)
__global__ void __launch_bounds__(160) gtoGK(const float* __restrict__ dist,
                                             const int* __restrict__ qn,
                                             const int* __restrict__ ao,
                                             const float* __restrict__ zeta) {
    extern __shared__ float sm[];
    float* tile = sm;                    // [128][68]
    float* zs   = sm + 128*68;
    int*   qs   = (int*)(zs + 64);
    int tid = threadIdx.x;
    int b   = blockIdx.y;

    if (tid < 64) {
        qs[tid] = qn[b*NA + tid];
        zs[tid] = zeta[ao[b*NA + tid]];
    }

    int ti = 0, tj = 0;
    {
        int t = tid;
        while (ti < 16 && t >= 16 - ti) { t -= 16 - ti; ti++; }
        tj = ti + t;
    }
    bool active = (tid < 136);

    float C[4][4];
    #pragma unroll
    for (int r = 0; r < 4; r++)
        #pragma unroll
        for (int c = 0; c < 4; c++) C[r][c] = 0.f;

    __syncthreads();

    for (int tl = blockIdx.x; tl < NG/128; tl += gridDim.x) {
        long base = ((long)b*NG + (long)tl*128) * NA;
        for (int i = tid; i < 128*16; i += 160) {
            int p = i >> 4, c = i & 15;
            float4 dv = *(const float4*)(dist + base + (long)p*NA + 4*c);
            float4 gv;
            gv.x = gto_val(dv.x, qs[4*c+0], zs[4*c+0]);
            gv.y = gto_val(dv.y, qs[4*c+1], zs[4*c+1]);
            gv.z = gto_val(dv.z, qs[4*c+2], zs[4*c+2]);
            gv.w = gto_val(dv.w, qs[4*c+3], zs[4*c+3]);
            *(float4*)&tile[p*68 + 4*c] = gv;
        }
        __syncthreads();
        if (active) {
            #pragma unroll 4
            for (int k = 0; k < 128; k++) {
                float4 ai = *(const float4*)&tile[k*68 + 4*ti];
                float4 aj = *(const float4*)&tile[k*68 + 4*tj];
                fma4(C[0], ai.x, aj); fma4(C[1], ai.y, aj);
                fma4(C[2], ai.z, aj); fma4(C[3], ai.w, aj);
            }
        }
        __syncthreads();
    }

    if (active) {
        float* Gb = g_G + b*4096;
        if (ti == tj) {
            #pragma unroll
            for (int r = 0; r < 4; r++)
                #pragma unroll
                for (int c = 0; c < 4; c++)
                    atomicAdd(&Gb[(4*ti + r)*64 + 4*tj + c], C[r][c]);
        } else {
            #pragma unroll
            for (int r = 0; r < 4; r++)
                #pragma unroll
                for (int c = 0; c < 4; c++) {
                    atomicAdd(&Gb[(4*ti + r)*64 + 4*tj + c], C[r][c]);
                    atomicAdd(&Gb[(4*tj + c)*64 + 4*ti + r], C[r][c]);
                }
        }
    }
}

// ---------- fused prep: ceff -> monorm -> packed M, all in smem ----------
#define PF_SMEM ((4096 + 8448 + 64 + 128 + 128 + 256) * 4 + 64*4)
__global__ void __launch_bounds__(256) prepFK(const int* __restrict__ ao,
                                              const float* __restrict__ coef,
                                              const float* __restrict__ Ne) {
    extern __shared__ float sm[];
    float* Gs    = sm;                    // 4096
    float* ceffS = Gs + 4096;             // 64*132, [a*132+d]
    float* rg    = ceffS + 8448;          // 64
    float* rc    = rg + 64;               // 128
    float* inv   = rc + 128;              // 128
    float* mpart = inv + 128;             // 256
    int*   aos   = (int*)(mpart + 256);   // 64
    int b = blockIdx.x, tid = threadIdx.x;

    for (int i = tid; i < 4096; i += 256) Gs[i] = g_G[b*4096 + i];
    if (tid < 64) aos[tid] = ao[b*NA + tid];
    __syncthreads();
    if (tid < 64) rg[tid] = 1.f / fmaxf(sqrtf(Gs[tid*64 + tid]), 1e-12f);

    for (int i = tid; i < 64*128; i += 256) {
        int a = i >> 7, d = i & 127;
        ceffS[a*132 + d] = coef[aos[a]*ND + d];
    }
    __syncthreads();

    if (tid < 128) {
        float cn = 0.f;
        #pragma unroll 8
        for (int a = 0; a < 64; a++) { float c = ceffS[a*132 + tid]; cn = fmaf(c, c, cn); }
        rc[tid] = 1.f / fmaxf(sqrtf(cn), 1e-12f);
    }
    __syncthreads();
    for (int i = tid; i < 64*128; i += 256) {
        int a = i >> 7, d = i & 127;
        ceffS[a*132 + d] *= rc[d] * rg[a];
    }
    __syncthreads();

    {
        int d = tid & 127, h = tid >> 7;
        float c[64];
        #pragma unroll
        for (int a = 0; a < 64; a++) c[a] = ceffS[a*132 + d];
        float m = 0.f;
        int i0 = 32*h;
        for (int i = i0; i < i0 + 32; i++) {
            const float4* row = (const float4*)&Gs[i*64];
            float y0 = 0.f, y1 = 0.f, y2 = 0.f, y3 = 0.f;
            #pragma unroll
            for (int k = 0; k < 4; k++) {
                float4 ga = row[k],     gb = row[k+4];
                float4 gc = row[k+8],   gd = row[k+12];
                y0 = fmaf(ga.x, c[4*k+0],  y0); y0 = fmaf(ga.y, c[4*k+1],  y0);
                y0 = fmaf(ga.z, c[4*k+2],  y0); y0 = fmaf(ga.w, c[4*k+3],  y0);
                y1 = fmaf(gb.x, c[16+4*k+0], y1); y1 = fmaf(gb.y, c[16+4*k+1], y1);
                y1 = fmaf(gb.z, c[16+4*k+2], y1); y1 = fmaf(gb.w, c[16+4*k+3], y1);
                y2 = fmaf(gc.x, c[32+4*k+0], y2); y2 = fmaf(gc.y, c[32+4*k+1], y2);
                y2 = fmaf(gc.z, c[32+4*k+2], y2); y2 = fmaf(gc.w, c[32+4*k+3], y2);
                y3 = fmaf(gd.x, c[48+4*k+0], y3); y3 = fmaf(gd.y, c[48+4*k+1], y3);
                y3 = fmaf(gd.z, c[48+4*k+2], y3); y3 = fmaf(gd.w, c[48+4*k+3], y3);
            }
            m = fmaf(y0 + y1 + y2 + y3, c[i], m);
        }
        mpart[h*128 + d] = m;
    }
    __syncthreads();
    if (tid < 128) {
        float m = mpart[tid] + mpart[128 + tid];
        float s2 = Ne[b] / (float)ND;
        inv[tid] = sqrtf(s2 / fmaxf(m, 1e-24f));
    }
    __syncthreads();
    for (int i = tid; i < 64*128; i += 256) {
        int a = i >> 7, d = i & 127;
        ceffS[a*132 + d] *= inv[d];
    }
    __syncthreads();

    if (tid < NTILE_SYM) {
        int ti = 0, tj = 0;
        {
            int t = tid;
            while (ti < 16 && t >= 16 - ti) { t -= 16 - ti; ti++; }
            tj = ti + t;
        }
        float acc[4][4];
        #pragma unroll
        for (int r = 0; r < 4; r++)
            #pragma unroll
            for (int c = 0; c < 4; c++) acc[r][c] = 0.f;
        for (int d = 0; d < 128; d++) {
            float ci[4], cj[4];
            #pragma unroll
            for (int r = 0; r < 4; r++) ci[r] = ceffS[(4*ti + r)*132 + d];
            #pragma unroll
            for (int c = 0; c < 4; c++) cj[c] = ceffS[(4*tj + c)*132 + d];
            #pragma unroll
            for (int r = 0; r < 4; r++)
                #pragma unroll
                for (int c = 0; c < 4; c++) acc[r][c] = fmaf(ci[r], cj[c], acc[r][c]);
        }
        float sc = (ti == tj) ? 1.0f : 2.0f;
        float* dst = g_Mpk + b*NTILE_SYM*16 + tid*16;
        #pragma unroll
        for (int r = 0; r < 4; r++)
            #pragma unroll
            for (int c = 0; c < 4; c++) dst[r*4 + c] = acc[r][c] * sc;
    }
}

// ---------- pass 2: dens_g = gto^T M gto, g in registers, M broadcast ----------
#define DQ_SMEM ((DQP*68 + NTILE_SYM*16 + 64 + 64) * 4)
__global__ void __launch_bounds__(128, 5) densQK(const float* __restrict__ dist,
                                                 const int* __restrict__ qn,
                                                 const int* __restrict__ ao,
                                                 const float* __restrict__ zeta) {
    extern __shared__ float sm[];
    float* gt = sm;                        // [DQP][68]
    float* Mp = gt + DQP*68;               // 2176
    float* zs = Mp + NTILE_SYM*16;         // 64
    int*   qs = (int*)(zs + 64);           // 64
    int tid = threadIdx.x;
    int b   = blockIdx.y;
    int g0  = blockIdx.x * DQP;

    if (tid < 64) {
        qs[tid] = qn[b*NA + tid];
        zs[tid] = zeta[ao[b*NA + tid]];
    }
    for (int i = tid; i < NTILE_SYM*16; i += 128) Mp[i] = g_Mpk[b*NTILE_SYM*16 + i];
    __syncthreads();

    long base = ((long)b*NG + g0) * NA;
    for (int i = tid; i < DQP*16; i += 128) {
        int p = i >> 4, c = i & 15;
        float4 dv = *(const float4*)(dist + base + (long)p*NA + 4*c);
        float4 gv;
        gv.x = gto_val(dv.x, qs[4*c+0], zs[4*c+0]);
        gv.y = gto_val(dv.y, qs[4*c+1], zs[4*c+1]);
        gv.z = gto_val(dv.z, qs[4*c+2], zs[4*c+2]);
        gv.w = gto_val(dv.w, qs[4*c+3], zs[4*c+3]);
        *(float4*)&gt[p*68 + 4*c] = gv;
    }
    __syncthreads();

    // g into registers (one pass, conflict-free with pad 68)
    float g[64];
    {
        const float* gp = gt + tid*68;
        #pragma unroll
        for (int k = 0; k < 16; k++) {
            float4 v = *(const float4*)(gp + 4*k);
            g[4*k+0] = v.x; g[4*k+1] = v.y; g[4*k+2] = v.z; g[4*k+3] = v.w;
        }
    }

    const float4* Mt = (const float4*)Mp;  // warp-uniform broadcasts
    float dens = 0.f;
    int t = 0;
    #pragma unroll
    for (int ti = 0; ti < 16; ti++) {
        float y0 = 0.f, y1 = 0.f, y2 = 0.f, y3 = 0.f;
        #pragma unroll
        for (int tj = ti; tj < 16; tj++, t++) {
            float4 m0 = Mt[4*t+0], m1 = Mt[4*t+1], m2 = Mt[4*t+2], m3 = Mt[4*t+3];
            float gj0 = g[4*tj+0], gj1 = g[4*tj+1], gj2 = g[4*tj+2], gj3 = g[4*tj+3];
            y0 = fmaf(m0.x, gj0, y0); y0 = fmaf(m0.y, gj1, y0);
            y0 = fmaf(m0.z, gj2, y0); y0 = fmaf(m0.w, gj3, y0);
            y1 = fmaf(m1.x, gj0, y1); y1 = fmaf(m1.y, gj1, y1);
            y1 = fmaf(m1.z, gj2, y1); y1 = fmaf(m1.w, gj3, y1);
            y2 = fmaf(m2.x, gj0, y2); y2 = fmaf(m2.y, gj1, y2);
            y2 = fmaf(m2.z, gj2, y2); y2 = fmaf(m2.w, gj3, y2);
            y3 = fmaf(m3.x, gj0, y3); y3 = fmaf(m3.y, gj1, y3);
            y3 = fmaf(m3.z, gj2, y3); y3 = fmaf(m3.w, gj3, y3);
        }
        float s = g[4*ti+0]*y0 + g[4*ti+1]*y1;
        s = fmaf(g[4*ti+2], y2, s);
        s = fmaf(g[4*ti+3], y3, s);
        dens += s;
    }
    g_dens[(long)b*NG + g0 + tid] = dens;

    float mx = dens;
    #pragma unroll
    for (int off = 16; off; off >>= 1)
        mx = fmaxf(mx, __shfl_xor_sync(0xffffffffu, mx, off));
    if ((tid & 31) == 0) atomicMax(&g_densmax_u, __float_as_uint(mx));
}

// ---------- table: phi at NT_TAB nodes over [0, densmax] ----------
__global__ void __launch_bounds__(256) tableK(const float* __restrict__ wfb,
                                              const float* __restrict__ wpw) {
    extern __shared__ float sm[];
    float* W1   = sm;
    float* W2   = W1 + ND*ND;
    float* bufA = W2 + ND*ND;
    float* bufB = bufA + GT*ND;
    float* us   = bufB + GT*BSTRIDE;
    float* ts   = us  + ND;
    float* b1s  = ts  + ND;
    float* b2s  = b1s + ND;
    float* wps  = b2s + ND;
    int tid = threadIdx.x;

    for (int i = tid; i < ND*ND; i += 256) { W1[i] = g_W1t[i]; W2[i] = g_W2t[i]; }
    if (tid < ND) {
        us[tid]  = g_u[tid];
        ts[tid]  = g_t[tid];
        b1s[tid] = wfb[ND + tid];
        b2s[tid] = wfb[2*ND + tid];
        wps[tid] = wpw[tid];
    }
    float h = __uint_as_float(g_densmax_u) / (float)(NT_TAB - 1);
    __syncthreads();

    int t0 = blockIdx.x * GT;
    for (int i = tid; i < GT*ND; i += 256) {
        int g = i >> 7, e = i & 127;
        float x = (float)(t0 + g) * h;
        bufA[i] = fmaxf(fmaf(x, us[e], ts[e]), 0.f);
    }
    __syncthreads();

    int eq = tid & 31, gq = tid >> 5;
    float acc[8][4];
    {
        float4 bb = *(const float4*)&b1s[4*eq];
        #pragma unroll
        for (int r = 0; r < 8; r++) { acc[r][0]=bb.x; acc[r][1]=bb.y; acc[r][2]=bb.z; acc[r][3]=bb.w; }
    }
    #pragma unroll 4
    for (int d4 = 0; d4 < 32; d4++) {
        float4 w[4];
        #pragma unroll
        for (int k = 0; k < 4; k++) w[k] = *(const float4*)&W1[(4*d4 + k)*ND + 4*eq];
        #pragma unroll
        for (int r = 0; r < 8; r++) {
            float4 v = *(const float4*)&bufA[(gq*8 + r)*ND + 4*d4];
            fma4(acc[r], v.x, w[0]); fma4(acc[r], v.y, w[1]);
            fma4(acc[r], v.z, w[2]); fma4(acc[r], v.w, w[3]);
        }
    }
    #pragma unroll
    for (int r = 0; r < 8; r++) {
        float4 o = make_float4(fmaxf(acc[r][0],0.f), fmaxf(acc[r][1],0.f),
                               fmaxf(acc[r][2],0.f), fmaxf(acc[r][3],0.f));
        *(float4*)&bufB[(gq*8 + r)*BSTRIDE + 4*eq] = o;
    }
    __syncthreads();

    {
        float4 bb = *(const float4*)&b2s[4*eq];
        #pragma unroll
        for (int r = 0; r < 8; r++) { acc[r][0]=bb.x; acc[r][1]=bb.y; acc[r][2]=bb.z; acc[r][3]=bb.w; }
    }
    #pragma unroll 4
    for (int d4 = 0; d4 < 32; d4++) {
        float4 w[4];
        #pragma unroll
        for (int k = 0; k < 4; k++) w[k] = *(const float4*)&W2[(4*d4 + k)*ND + 4*eq];
        #pragma unroll
        for (int r = 0; r < 8; r++) {
            float4 v = *(const float4*)&bufB[(gq*8 + r)*BSTRIDE + 4*d4];
            fma4(acc[r], v.x, w[0]); fma4(acc[r], v.y, w[1]);
            fma4(acc[r], v.z, w[2]); fma4(acc[r], v.w, w[3]);
        }
    }
    float4 wp4 = *(const float4*)&wps[4*eq];
    #pragma unroll
    for (int r = 0; r < 8; r++) {
        float v = fmaxf(acc[r][0],0.f)*wp4.x + fmaxf(acc[r][1],0.f)*wp4.y
                + fmaxf(acc[r][2],0.f)*wp4.z + fmaxf(acc[r][3],0.f)*wp4.w;
        #pragma unroll
        for (int off = 16; off; off >>= 1) v += __shfl_xor_sync(0xffffffffu, v, off);
        if (eq == 0) g_table[t0 + gq*8 + r] = v;
    }
}

// ---------- final: E[b] += sum_g lerp(table, dens) ----------
__global__ void __launch_bounds__(256) sumK(float* __restrict__ out) {
    extern __shared__ float T[];
    float* red = T + NT_TAB;
    int tid = threadIdx.x;
    for (int i = tid; i < NT_TAB/4; i += 256)
        ((float4*)T)[i] = ((const float4*)g_table)[i];
    __syncthreads();
    float invh = (float)(NT_TAB - 1) / __uint_as_float(g_densmax_u);
    int b = blockIdx.y;
    const int chunk = NG / 8;
    long base = (long)b*NG + blockIdx.x*chunk;
    float acc = 0.f;
    for (int i = tid; i < chunk; i += 256) {
        float dn = g_dens[base + i];
        float t  = dn * invh;
        int ix = min((int)t, NT_TAB - 2);
        float f = t - (float)ix;
        acc += fmaf(f, T[ix+1] - T[ix], T[ix]);
    }
    #pragma unroll
    for (int off = 16; off; off >>= 1) acc += __shfl_xor_sync(0xffffffffu, acc, off);
    if ((tid & 31) == 0) red[tid >> 5] = acc;
    __syncthreads();
    if (tid == 0) {
        float s = 0.f;
        #pragma unroll
        for (int w = 0; w < 8; w++) s += red[w];
        atomicAdd(&out[b], s);
    }
}

extern "C" void kernel_launch(void* const* d_in, const int* in_sizes, int n_in,
                              void* d_out, int out_size) {
    const float* dist  = (const float*)d_in[0];
    const int*   qn    = (const int*)  d_in[1];
    const int*   ao    = (const int*)  d_in[2];
    const float* Ne    = (const float*)d_in[3];
    const float* coef  = (const float*)d_in[4];
    const float* zeta  = (const float*)d_in[5];
    const float* wprew = (const float*)d_in[6];
    const float* wpreb = (const float*)d_in[7];
    const float* wfw   = (const float*)d_in[8];
    const float* wfb   = (const float*)d_in[9];
    const float* wpw   = (const float*)d_in[10];
    const float* wpb   = (const float*)d_in[11];
    float* out = (float*)d_out;

    const int tabSmem = (ND*ND*2 + GT*ND + GT*BSTRIDE + ND*5) * 4;
    const int sumSmem = (NT_TAB + 8) * 4;
    cudaFuncSetAttribute(gtoGK,  cudaFuncAttributeMaxDynamicSharedMemorySize, G_SMEM);
    cudaFuncSetAttribute(prepFK, cudaFuncAttributeMaxDynamicSharedMemorySize, PF_SMEM);
    cudaFuncSetAttribute(densQK, cudaFuncAttributeMaxDynamicSharedMemorySize, DQ_SMEM);
    cudaFuncSetAttribute(tableK, cudaFuncAttributeMaxDynamicSharedMemorySize, tabSmem);
    cudaFuncSetAttribute(sumK,   cudaFuncAttributeMaxDynamicSharedMemorySize, sumSmem);

    setupK<<<12, 256>>>(out, wpb, wprew, wpreb, wfw, wfb);
    gtoGK<<<dim3(128, NB), 160, G_SMEM>>>(dist, qn, ao, zeta);
    prepFK<<<NB, 256, PF_SMEM>>>(ao, coef, Ne);
    densQK<<<dim3(NG/DQP, NB), 128, DQ_SMEM>>>(dist, qn, ao, zeta);
    tableK<<<NT_TAB/GT, 256, tabSmem>>>(wfb, wpw);
    sumK<<<dim3(8, NB), 256, sumSmem>>>(out);
}

// round 9
// speedup vs baseline: 4.3152x; 1.0364x over previous
#include <cuda_runtime.h>
#include <math.h>

#define NB 8
#define NG 32768
#define NA 64
#define ND 128
#define GT 64
#define BSTRIDE 132
#define NT_TAB 8192
#define NTILE_SYM 136      // upper-triangular 4x4 tiles of 64x64
#define DQP 64             // points per densQK block

// ---- scratch (static device allocations are allowed) ----
__device__ float g_G[NB*64*64];            // gto^T gto per molecule
__device__ float g_Mpk[NB*NTILE_SYM*16];   // packed symmetric M (off-diag doubled)
__device__ float g_dens[NB*NG];
__device__ float g_table[NT_TAB];
__device__ unsigned g_densmax_u;
__device__ float g_u[ND];
__device__ float g_t[ND];
__device__ float g_W1t[ND*ND];
__device__ float g_W2t[ND*ND];

static __device__ __forceinline__ void fma4(float* acc, float v, float4 w) {
    acc[0] = fmaf(v, w.x, acc[0]);
    acc[1] = fmaf(v, w.y, acc[1]);
    acc[2] = fmaf(v, w.z, acc[2]);
    acc[3] = fmaf(v, w.w, acc[3]);
}

static __device__ __forceinline__ float gto_val(float d, int q, float z) {
    float zd = z * d;
    float p  = (q == 0) ? 1.0f : ((q == 1) ? d : d*d);
    return p * __expf(-zd*zd);
}

// packed upper-tri tile index for 4x4 tile (TI,TJ), TI<=TJ, 16x16 tile grid
static __device__ __forceinline__ int tsym(int TI, int TJ) {
    return TI*16 - (TI*(TI+1))/2 + TJ;
}

// ---------- setup ----------
__global__ void setupK(float* out, const float* __restrict__ wpb,
                       const float* __restrict__ wprew, const float* __restrict__ wpreb,
                       const float* __restrict__ wfw,   const float* __restrict__ wfb) {
    int bid = blockIdx.x, tid = threadIdx.x;
    if (bid == 0) {
        if (tid < NB) out[tid] = wpb[0];
        if (tid == 0) g_densmax_u = 0u;
    } else if (bid == 1) {
        if (tid < ND) {
            int e = tid;
            float u = 0.f, t = 0.f;
            for (int d = 0; d < ND; d++) {
                float w = wfw[e*ND + d];
                u = fmaf(w, wprew[d], u);
                t = fmaf(w, wpreb[d], t);
            }
            g_u[e] = u;
            g_t[e] = t + wfb[e];
        }
    } else if (bid <= 3) {
        float* dst = (bid == 2) ? g_W1t : g_W2t;
        const float* src = wfw + (bid - 1) * ND * ND;
        for (int i = tid; i < ND*ND; i += 256) {
            int e = i >> 7, d = i & 127;
            dst[d*ND + e] = src[i];
        }
    } else {
        int b = bid - 4;
        for (int i = tid; i < 64*64; i += 256) g_G[b*4096 + i] = 0.f;
    }
}

// ---------- pass 1: gto from dist, syrk G += gto^T gto ----------
#define G_SMEM ((128*68 + 64 + 64) * 4)
__global__ void __launch_bounds__(160) gtoGK(const float* __restrict__ dist,
                                             const int* __restrict__ qn,
                                             const int* __restrict__ ao,
                                             const float* __restrict__ zeta) {
    extern __shared__ float sm[];
    float* tile = sm;                    // [128][68]
    float* zs   = sm + 128*68;
    int*   qs   = (int*)(zs + 64);
    int tid = threadIdx.x;
    int b   = blockIdx.y;

    if (tid < 64) {
        qs[tid] = qn[b*NA + tid];
        zs[tid] = zeta[ao[b*NA + tid]];
    }

    int ti = 0, tj = 0;
    {
        int t = tid;
        while (ti < 16 && t >= 16 - ti) { t -= 16 - ti; ti++; }
        tj = ti + t;
    }
    bool active = (tid < 136);

    float C[4][4];
    #pragma unroll
    for (int r = 0; r < 4; r++)
        #pragma unroll
        for (int c = 0; c < 4; c++) C[r][c] = 0.f;

    __syncthreads();

    for (int tl = blockIdx.x; tl < NG/128; tl += gridDim.x) {
        long base = ((long)b*NG + (long)tl*128) * NA;
        for (int i = tid; i < 128*16; i += 160) {
            int p = i >> 4, c = i & 15;
            float4 dv = *(const float4*)(dist + base + (long)p*NA + 4*c);
            float4 gv;
            gv.x = gto_val(dv.x, qs[4*c+0], zs[4*c+0]);
            gv.y = gto_val(dv.y, qs[4*c+1], zs[4*c+1]);
            gv.z = gto_val(dv.z, qs[4*c+2], zs[4*c+2]);
            gv.w = gto_val(dv.w, qs[4*c+3], zs[4*c+3]);
            *(float4*)&tile[p*68 + 4*c] = gv;
        }
        __syncthreads();
        if (active) {
            #pragma unroll 4
            for (int k = 0; k < 128; k++) {
                float4 ai = *(const float4*)&tile[k*68 + 4*ti];
                float4 aj = *(const float4*)&tile[k*68 + 4*tj];
                fma4(C[0], ai.x, aj); fma4(C[1], ai.y, aj);
                fma4(C[2], ai.z, aj); fma4(C[3], ai.w, aj);
            }
        }
        __syncthreads();
    }

    if (active) {
        float* Gb = g_G + b*4096;
        if (ti == tj) {
            #pragma unroll
            for (int r = 0; r < 4; r++)
                #pragma unroll
                for (int c = 0; c < 4; c++)
                    atomicAdd(&Gb[(4*ti + r)*64 + 4*tj + c], C[r][c]);
        } else {
            #pragma unroll
            for (int r = 0; r < 4; r++)
                #pragma unroll
                for (int c = 0; c < 4; c++) {
                    atomicAdd(&Gb[(4*ti + r)*64 + 4*tj + c], C[r][c]);
                    atomicAdd(&Gb[(4*tj + c)*64 + 4*ti + r], C[r][c]);
                }
        }
    }
}

// ---------- fused prep: ceff -> monorm -> packed M ----------
#define PF_SMEM ((4096 + 8448 + 64 + 128 + 128 + 256) * 4 + 64*4)
__global__ void __launch_bounds__(256) prepFK(const int* __restrict__ ao,
                                              const float* __restrict__ coef,
                                              const float* __restrict__ Ne) {
    extern __shared__ float sm[];
    float* Gs    = sm;                    // 4096
    float* ceffS = Gs + 4096;             // 64*132
    float* rg    = ceffS + 8448;          // 64
    float* rc    = rg + 64;               // 128
    float* inv   = rc + 128;              // 128
    float* mpart = inv + 128;             // 256
    int*   aos   = (int*)(mpart + 256);   // 64
    int b = blockIdx.x, tid = threadIdx.x;

    for (int i = tid; i < 4096; i += 256) Gs[i] = g_G[b*4096 + i];
    if (tid < 64) aos[tid] = ao[b*NA + tid];
    __syncthreads();
    if (tid < 64) rg[tid] = 1.f / fmaxf(sqrtf(Gs[tid*64 + tid]), 1e-12f);

    for (int i = tid; i < 64*128; i += 256) {
        int a = i >> 7, d = i & 127;
        ceffS[a*132 + d] = coef[aos[a]*ND + d];
    }
    __syncthreads();

    if (tid < 128) {
        float cn = 0.f;
        #pragma unroll 8
        for (int a = 0; a < 64; a++) { float c = ceffS[a*132 + tid]; cn = fmaf(c, c, cn); }
        rc[tid] = 1.f / fmaxf(sqrtf(cn), 1e-12f);
    }
    __syncthreads();
    for (int i = tid; i < 64*128; i += 256) {
        int a = i >> 7, d = i & 127;
        ceffS[a*132 + d] *= rc[d] * rg[a];
    }
    __syncthreads();

    {
        int d = tid & 127, h = tid >> 7;
        float c[64];
        #pragma unroll
        for (int a = 0; a < 64; a++) c[a] = ceffS[a*132 + d];
        float m = 0.f;
        int i0 = 32*h;
        for (int i = i0; i < i0 + 32; i++) {
            const float4* row = (const float4*)&Gs[i*64];
            float y0 = 0.f, y1 = 0.f, y2 = 0.f, y3 = 0.f;
            #pragma unroll
            for (int k = 0; k < 4; k++) {
                float4 ga = row[k],     gb = row[k+4];
                float4 gc = row[k+8],   gd = row[k+12];
                y0 = fmaf(ga.x, c[4*k+0],  y0); y0 = fmaf(ga.y, c[4*k+1],  y0);
                y0 = fmaf(ga.z, c[4*k+2],  y0); y0 = fmaf(ga.w, c[4*k+3],  y0);
                y1 = fmaf(gb.x, c[16+4*k+0], y1); y1 = fmaf(gb.y, c[16+4*k+1], y1);
                y1 = fmaf(gb.z, c[16+4*k+2], y1); y1 = fmaf(gb.w, c[16+4*k+3], y1);
                y2 = fmaf(gc.x, c[32+4*k+0], y2); y2 = fmaf(gc.y, c[32+4*k+1], y2);
                y2 = fmaf(gc.z, c[32+4*k+2], y2); y2 = fmaf(gc.w, c[32+4*k+3], y2);
                y3 = fmaf(gd.x, c[48+4*k+0], y3); y3 = fmaf(gd.y, c[48+4*k+1], y3);
                y3 = fmaf(gd.z, c[48+4*k+2], y3); y3 = fmaf(gd.w, c[48+4*k+3], y3);
            }
            m = fmaf(y0 + y1 + y2 + y3, c[i], m);
        }
        mpart[h*128 + d] = m;
    }
    __syncthreads();
    if (tid < 128) {
        float m = mpart[tid] + mpart[128 + tid];
        float s2 = Ne[b] / (float)ND;
        inv[tid] = sqrtf(s2 / fmaxf(m, 1e-24f));
    }
    __syncthreads();
    for (int i = tid; i < 64*128; i += 256) {
        int a = i >> 7, d = i & 127;
        ceffS[a*132 + d] *= inv[d];
    }
    __syncthreads();

    if (tid < NTILE_SYM) {
        int ti = 0, tj = 0;
        {
            int t = tid;
            while (ti < 16 && t >= 16 - ti) { t -= 16 - ti; ti++; }
            tj = ti + t;
        }
        float acc[4][4];
        #pragma unroll
        for (int r = 0; r < 4; r++)
            #pragma unroll
            for (int c = 0; c < 4; c++) acc[r][c] = 0.f;
        for (int d = 0; d < 128; d++) {
            float ci[4], cj[4];
            #pragma unroll
            for (int r = 0; r < 4; r++) ci[r] = ceffS[(4*ti + r)*132 + d];
            #pragma unroll
            for (int c = 0; c < 4; c++) cj[c] = ceffS[(4*tj + c)*132 + d];
            #pragma unroll
            for (int r = 0; r < 4; r++)
                #pragma unroll
                for (int c = 0; c < 4; c++) acc[r][c] = fmaf(ci[r], cj[c], acc[r][c]);
        }
        float sc = (ti == tj) ? 1.0f : 2.0f;
        float* dst = g_Mpk + b*NTILE_SYM*16 + tid*16;
        #pragma unroll
        for (int r = 0; r < 4; r++)
            #pragma unroll
            for (int c = 0; c < 4; c++) dst[r*4 + c] = acc[r][c] * sc;
    }
}

// ---------- pass 2: dens = g^T M g, thread-pair per point ----------
#define DQ_SMEM ((DQP*68 + NTILE_SYM*16 + 64 + DQP) * 4 + 64*4)
__global__ void __launch_bounds__(128, 8) densQK(const float* __restrict__ dist,
                                                 const int* __restrict__ qn,
                                                 const int* __restrict__ ao,
                                                 const float* __restrict__ zeta) {
    extern __shared__ float sm[];
    float* gt = sm;                        // [DQP][68]
    float* Mp = gt + DQP*68;               // 2176
    float* zs = Mp + NTILE_SYM*16;         // 64
    float* pd = zs + 64;                   // DQP partials
    int*   qs = (int*)(pd + DQP);          // 64
    int tid = threadIdx.x;
    int b   = blockIdx.y;
    int g0  = blockIdx.x * DQP;
    int p   = tid & 63;
    int h   = tid >> 6;                    // warp-uniform (warps 0,1 -> 0; 2,3 -> 1)

    if (tid < 64) {
        qs[tid] = qn[b*NA + tid];
        zs[tid] = zeta[ao[b*NA + tid]];
    }
    for (int i = tid; i < NTILE_SYM*16; i += 128) Mp[i] = g_Mpk[b*NTILE_SYM*16 + i];
    __syncthreads();

    long base = ((long)b*NG + g0) * NA;
    for (int i = tid; i < DQP*16; i += 128) {
        int pp = i >> 4, c = i & 15;
        float4 dv = *(const float4*)(dist + base + (long)pp*NA + 4*c);
        float4 gv;
        gv.x = gto_val(dv.x, qs[4*c+0], zs[4*c+0]);
        gv.y = gto_val(dv.y, qs[4*c+1], zs[4*c+1]);
        gv.z = gto_val(dv.z, qs[4*c+2], zs[4*c+2]);
        gv.w = gto_val(dv.w, qs[4*c+3], zs[4*c+3]);
        *(float4*)&gt[pp*68 + 4*c] = gv;
    }
    __syncthreads();

    // own half into registers
    float g[32];
    {
        const float* gp = gt + p*68 + 32*h;
        #pragma unroll
        for (int k = 0; k < 8; k++) {
            float4 v = *(const float4*)(gp + 4*k);
            g[4*k+0] = v.x; g[4*k+1] = v.y; g[4*k+2] = v.z; g[4*k+3] = v.w;
        }
    }

    const float4* Mt = (const float4*)Mp;
    float dens = 0.f;

    // own-half symmetric QF: global tiles (8h+a, 8h+bb), a<=bb
    #pragma unroll
    for (int a = 0; a < 8; a++) {
        float y0 = 0.f, y1 = 0.f, y2 = 0.f, y3 = 0.f;
        #pragma unroll
        for (int bb = a; bb < 8; bb++) {
            int t = tsym(8*h + a, 8*h + bb);
            float4 m0 = Mt[4*t+0], m1 = Mt[4*t+1], m2 = Mt[4*t+2], m3 = Mt[4*t+3];
            float gj0 = g[4*bb+0], gj1 = g[4*bb+1], gj2 = g[4*bb+2], gj3 = g[4*bb+3];
            y0 = fmaf(m0.x, gj0, y0); y0 = fmaf(m0.y, gj1, y0);
            y0 = fmaf(m0.z, gj2, y0); y0 = fmaf(m0.w, gj3, y0);
            y1 = fmaf(m1.x, gj0, y1); y1 = fmaf(m1.y, gj1, y1);
            y1 = fmaf(m1.z, gj2, y1); y1 = fmaf(m1.w, gj3, y1);
            y2 = fmaf(m2.x, gj0, y2); y2 = fmaf(m2.y, gj1, y2);
            y2 = fmaf(m2.z, gj2, y2); y2 = fmaf(m2.w, gj3, y2);
            y3 = fmaf(m3.x, gj0, y3); y3 = fmaf(m3.y, gj1, y3);
            y3 = fmaf(m3.z, gj2, y3); y3 = fmaf(m3.w, gj3, y3);
        }
        float s = g[4*a+0]*y0 + g[4*a+1]*y1;
        s = fmaf(g[4*a+2], y2, s);
        s = fmaf(g[4*a+3], y3, s);
        dens += s;
    }

    // cross block: tiles (a, 8+bb), a,bb in [0,8) -- split by bb range
    if (h == 0) {
        // this thread owns rows (H0). bb in [0,4): w_c = sum_a gi^T M; dens += w . gj(smem)
        #pragma unroll
        for (int bb = 0; bb < 4; bb++) {
            float4 gj = *(const float4*)&gt[p*68 + 32 + 4*bb];
            float w0 = 0.f, w1 = 0.f, w2 = 0.f, w3 = 0.f;
            #pragma unroll
            for (int a = 0; a < 8; a++) {
                int t = tsym(a, 8 + bb);
                float4 m0 = Mt[4*t+0], m1 = Mt[4*t+1], m2 = Mt[4*t+2], m3 = Mt[4*t+3];
                float gi0 = g[4*a+0], gi1 = g[4*a+1], gi2 = g[4*a+2], gi3 = g[4*a+3];
                w0 = fmaf(m0.x, gi0, w0); w1 = fmaf(m0.y, gi0, w1);
                w2 = fmaf(m0.z, gi0, w2); w3 = fmaf(m0.w, gi0, w3);
                w0 = fmaf(m1.x, gi1, w0); w1 = fmaf(m1.y, gi1, w1);
                w2 = fmaf(m1.z, gi1, w2); w3 = fmaf(m1.w, gi1, w3);
                w0 = fmaf(m2.x, gi2, w0); w1 = fmaf(m2.y, gi2, w1);
                w2 = fmaf(m2.z, gi2, w2); w3 = fmaf(m2.w, gi2, w3);
                w0 = fmaf(m3.x, gi3, w0); w1 = fmaf(m3.y, gi3, w1);
                w2 = fmaf(m3.z, gi3, w2); w3 = fmaf(m3.w, gi3, w3);
            }
            float s = w0*gj.x + w1*gj.y;
            s = fmaf(w2, gj.z, s);
            s = fmaf(w3, gj.w, s);
            dens += s;
        }
    } else {
        // this thread owns cols (H1: g[4bb+c] = comp 32+4bb+c). bb in [4,8).
        #pragma unroll
        for (int a = 0; a < 8; a++) {
            float v0 = 0.f, v1 = 0.f, v2 = 0.f, v3 = 0.f;
            #pragma unroll
            for (int bb = 4; bb < 8; bb++) {
                int t = tsym(a, 8 + bb);
                float4 m0 = Mt[4*t+0], m1 = Mt[4*t+1], m2 = Mt[4*t+2], m3 = Mt[4*t+3];
                float gj0 = g[4*bb+0], gj1 = g[4*bb+1], gj2 = g[4*bb+2], gj3 = g[4*bb+3];
                v0 = fmaf(m0.x, gj0, v0); v0 = fmaf(m0.y, gj1, v0);
                v0 = fmaf(m0.z, gj2, v0); v0 = fmaf(m0.w, gj3, v0);
                v1 = fmaf(m1.x, gj0, v1); v1 = fmaf(m1.y, gj1, v1);
                v1 = fmaf(m1.z, gj2, v1); v1 = fmaf(m1.w, gj3, v1);
                v2 = fmaf(m2.x, gj0, v2); v2 = fmaf(m2.y, gj1, v2);
                v2 = fmaf(m2.z, gj2, v2); v2 = fmaf(m2.w, gj3, v2);
                v3 = fmaf(m3.x, gj0, v3); v3 = fmaf(m3.y, gj1, v3);
                v3 = fmaf(m3.z, gj2, v3); v3 = fmaf(m3.w, gj3, v3);
            }
            float4 gi = *(const float4*)&gt[p*68 + 4*a];
            float s = gi.x*v0 + gi.y*v1;
            s = fmaf(gi.z, v2, s);
            s = fmaf(gi.w, v3, s);
            dens += s;
        }
    }

    if (h == 1) pd[p] = dens;
    __syncthreads();
    if (h == 0) {
        float d = dens + pd[p];
        g_dens[(long)b*NG + g0 + p] = d;
        float mx = d;
        #pragma unroll
        for (int off = 16; off; off >>= 1)
            mx = fmaxf(mx, __shfl_xor_sync(0xffffffffu, mx, off));
        if ((tid & 31) == 0) atomicMax(&g_densmax_u, __float_as_uint(mx));
    }
}

// ---------- table: phi at NT_TAB nodes over [0, densmax] ----------
__global__ void __launch_bounds__(256) tableK(const float* __restrict__ wfb,
                                              const float* __restrict__ wpw) {
    extern __shared__ float sm[];
    float* W1   = sm;
    float* W2   = W1 + ND*ND;
    float* bufA = W2 + ND*ND;
    float* bufB = bufA + GT*ND;
    float* us   = bufB + GT*BSTRIDE;
    float* ts   = us  + ND;
    float* b1s  = ts  + ND;
    float* b2s  = b1s + ND;
    float* wps  = b2s + ND;
    int tid = threadIdx.x;

    for (int i = tid; i < ND*ND; i += 256) { W1[i] = g_W1t[i]; W2[i] = g_W2t[i]; }
    if (tid < ND) {
        us[tid]  = g_u[tid];
        ts[tid]  = g_t[tid];
        b1s[tid] = wfb[ND + tid];
        b2s[tid] = wfb[2*ND + tid];
        wps[tid] = wpw[tid];
    }
    float h = __uint_as_float(g_densmax_u) / (float)(NT_TAB - 1);
    __syncthreads();

    int t0 = blockIdx.x * GT;
    for (int i = tid; i < GT*ND; i += 256) {
        int g = i >> 7, e = i & 127;
        float x = (float)(t0 + g) * h;
        bufA[i] = fmaxf(fmaf(x, us[e], ts[e]), 0.f);
    }
    __syncthreads();

    int eq = tid & 31, gq = tid >> 5;
    float acc[8][4];
    {
        float4 bb = *(const float4*)&b1s[4*eq];
        #pragma unroll
        for (int r = 0; r < 8; r++) { acc[r][0]=bb.x; acc[r][1]=bb.y; acc[r][2]=bb.z; acc[r][3]=bb.w; }
    }
    #pragma unroll 4
    for (int d4 = 0; d4 < 32; d4++) {
        float4 w[4];
        #pragma unroll
        for (int k = 0; k < 4; k++) w[k] = *(const float4*)&W1[(4*d4 + k)*ND + 4*eq];
        #pragma unroll
        for (int r = 0; r < 8; r++) {
            float4 v = *(const float4*)&bufA[(gq*8 + r)*ND + 4*d4];
            fma4(acc[r], v.x, w[0]); fma4(acc[r], v.y, w[1]);
            fma4(acc[r], v.z, w[2]); fma4(acc[r], v.w, w[3]);
        }
    }
    #pragma unroll
    for (int r = 0; r < 8; r++) {
        float4 o = make_float4(fmaxf(acc[r][0],0.f), fmaxf(acc[r][1],0.f),
                               fmaxf(acc[r][2],0.f), fmaxf(acc[r][3],0.f));
        *(float4*)&bufB[(gq*8 + r)*BSTRIDE + 4*eq] = o;
    }
    __syncthreads();

    {
        float4 bb = *(const float4*)&b2s[4*eq];
        #pragma unroll
        for (int r = 0; r < 8; r++) { acc[r][0]=bb.x; acc[r][1]=bb.y; acc[r][2]=bb.z; acc[r][3]=bb.w; }
    }
    #pragma unroll 4
    for (int d4 = 0; d4 < 32; d4++) {
        float4 w[4];
        #pragma unroll
        for (int k = 0; k < 4; k++) w[k] = *(const float4*)&W2[(4*d4 + k)*ND + 4*eq];
        #pragma unroll
        for (int r = 0; r < 8; r++) {
            float4 v = *(const float4*)&bufB[(gq*8 + r)*BSTRIDE + 4*d4];
            fma4(acc[r], v.x, w[0]); fma4(acc[r], v.y, w[1]);
            fma4(acc[r], v.z, w[2]); fma4(acc[r], v.w, w[3]);
        }
    }
    float4 wp4 = *(const float4*)&wps[4*eq];
    #pragma unroll
    for (int r = 0; r < 8; r++) {
        float v = fmaxf(acc[r][0],0.f)*wp4.x + fmaxf(acc[r][1],0.f)*wp4.y
                + fmaxf(acc[r][2],0.f)*wp4.z + fmaxf(acc[r][3],0.f)*wp4.w;
        #pragma unroll
        for (int off = 16; off; off >>= 1) v += __shfl_xor_sync(0xffffffffu, v, off);
        if (eq == 0) g_table[t0 + gq*8 + r] = v;
    }
}

// ---------- final: E[b] += sum_g lerp(table, dens) ----------
__global__ void __launch_bounds__(256) sumK(float* __restrict__ out) {
    extern __shared__ float T[];
    float* red = T + NT_TAB;
    int tid = threadIdx.x;
    for (int i = tid; i < NT_TAB/4; i += 256)
        ((float4*)T)[i] = ((const float4*)g_table)[i];
    __syncthreads();
    float invh = (float)(NT_TAB - 1) / __uint_as_float(g_densmax_u);
    int b = blockIdx.y;
    const int chunk = NG / 8;
    long base = (long)b*NG + blockIdx.x*chunk;
    float acc = 0.f;
    for (int i = tid; i < chunk; i += 256) {
        float dn = g_dens[base + i];
        float t  = dn * invh;
        int ix = min((int)t, NT_TAB - 2);
        float f = t - (float)ix;
        acc += fmaf(f, T[ix+1] - T[ix], T[ix]);
    }
    #pragma unroll
    for (int off = 16; off; off >>= 1) acc += __shfl_xor_sync(0xffffffffu, acc, off);
    if ((tid & 31) == 0) red[tid >> 5] = acc;
    __syncthreads();
    if (tid == 0) {
        float s = 0.f;
        #pragma unroll
        for (int w = 0; w < 8; w++) s += red[w];
        atomicAdd(&out[b], s);
    }
}

extern "C" void kernel_launch(void* const* d_in, const int* in_sizes, int n_in,
                              void* d_out, int out_size) {
    const float* dist  = (const float*)d_in[0];
    const int*   qn    = (const int*)  d_in[1];
    const int*   ao    = (const int*)  d_in[2];
    const float* Ne    = (const float*)d_in[3];
    const float* coef  = (const float*)d_in[4];
    const float* zeta  = (const float*)d_in[5];
    const float* wprew = (const float*)d_in[6];
    const float* wpreb = (const float*)d_in[7];
    const float* wfw   = (const float*)d_in[8];
    const float* wfb   = (const float*)d_in[9];
    const float* wpw   = (const float*)d_in[10];
    const float* wpb   = (const float*)d_in[11];
    float* out = (float*)d_out;

    const int tabSmem = (ND*ND*2 + GT*ND + GT*BSTRIDE + ND*5) * 4;
    const int sumSmem = (NT_TAB + 8) * 4;
    cudaFuncSetAttribute(gtoGK,  cudaFuncAttributeMaxDynamicSharedMemorySize, G_SMEM);
    cudaFuncSetAttribute(prepFK, cudaFuncAttributeMaxDynamicSharedMemorySize, PF_SMEM);
    cudaFuncSetAttribute(densQK, cudaFuncAttributeMaxDynamicSharedMemorySize, DQ_SMEM);
    cudaFuncSetAttribute(tableK, cudaFuncAttributeMaxDynamicSharedMemorySize, tabSmem);
    cudaFuncSetAttribute(sumK,   cudaFuncAttributeMaxDynamicSharedMemorySize, sumSmem);

    setupK<<<12, 256>>>(out, wpb, wprew, wpreb, wfw, wfb);
    gtoGK<<<dim3(111, NB), 160, G_SMEM>>>(dist, qn, ao, zeta);
    prepFK<<<NB, 256, PF_SMEM>>>(ao, coef, Ne);
    densQK<<<dim3(NG/DQP, NB), 128, DQ_SMEM>>>(dist, qn, ao, zeta);
    tableK<<<NT_TAB/GT, 256, tabSmem>>>(wfb, wpw);
    sumK<<<dim3(8, NB), 256, sumSmem>>>(out);
}

// round 10
// speedup vs baseline: 4.3383x; 1.0053x over previous
#include <cuda_runtime.h>
#include <math.h>

#define NB 8
#define NG 32768
#define NA 64
#define ND 128
#define GT 64
#define BSTRIDE 132
#define NT_TAB 8192
#define NTILE_SYM 136      // upper-triangular 4x4 tiles of 64x64
#define DQP 128            // points per densQK block (2 per thread)

// ---- scratch (static device allocations are allowed) ----
__device__ float g_G[NB*64*64];            // gto^T gto per molecule
__device__ float g_Mpk[NB*NTILE_SYM*16];   // packed symmetric M (off-diag doubled)
__device__ float g_dens[NB*NG];
__device__ float g_table[NT_TAB];
__device__ unsigned g_densmax_u;
__device__ float g_u[ND];
__device__ float g_t[ND];
__device__ float g_W1t[ND*ND];
__device__ float g_W2t[ND*ND];

static __device__ __forceinline__ void fma4(float* acc, float v, float4 w) {
    acc[0] = fmaf(v, w.x, acc[0]);
    acc[1] = fmaf(v, w.y, acc[1]);
    acc[2] = fmaf(v, w.z, acc[2]);
    acc[3] = fmaf(v, w.w, acc[3]);
}

static __device__ __forceinline__ float gto_val(float d, int q, float z) {
    float zd = z * d;
    float p  = (q == 0) ? 1.0f : ((q == 1) ? d : d*d);
    return p * __expf(-zd*zd);
}

// packed upper-tri tile index for 4x4 tile (TI,TJ), TI<=TJ, 16x16 tile grid
static __device__ __forceinline__ int tsym(int TI, int TJ) {
    return TI*16 - (TI*(TI+1))/2 + TJ;
}

// ---------- setup ----------
__global__ void setupK(float* out, const float* __restrict__ wpb,
                       const float* __restrict__ wprew, const float* __restrict__ wpreb,
                       const float* __restrict__ wfw,   const float* __restrict__ wfb) {
    int bid = blockIdx.x, tid = threadIdx.x;
    if (bid == 0) {
        if (tid < NB) out[tid] = wpb[0];
        if (tid == 0) g_densmax_u = 0u;
    } else if (bid == 1) {
        if (tid < ND) {
            int e = tid;
            float u = 0.f, t = 0.f;
            for (int d = 0; d < ND; d++) {
                float w = wfw[e*ND + d];
                u = fmaf(w, wprew[d], u);
                t = fmaf(w, wpreb[d], t);
            }
            g_u[e] = u;
            g_t[e] = t + wfb[e];
        }
    } else if (bid <= 3) {
        float* dst = (bid == 2) ? g_W1t : g_W2t;
        const float* src = wfw + (bid - 1) * ND * ND;
        for (int i = tid; i < ND*ND; i += 256) {
            int e = i >> 7, d = i & 127;
            dst[d*ND + e] = src[i];
        }
    } else {
        int b = bid - 4;
        for (int i = tid; i < 64*64; i += 256) g_G[b*4096 + i] = 0.f;
    }
}

// ---------- pass 1: gto from dist, syrk G += gto^T gto ----------
#define G_SMEM ((128*68 + 64 + 64) * 4)
__global__ void __launch_bounds__(160) gtoGK(const float* __restrict__ dist,
                                             const int* __restrict__ qn,
                                             const int* __restrict__ ao,
                                             const float* __restrict__ zeta) {
    extern __shared__ float sm[];
    float* tile = sm;                    // [128][68]
    float* zs   = sm + 128*68;
    int*   qs   = (int*)(zs + 64);
    int tid = threadIdx.x;
    int b   = blockIdx.y;

    if (tid < 64) {
        qs[tid] = qn[b*NA + tid];
        zs[tid] = zeta[ao[b*NA + tid]];
    }

    int ti = 0, tj = 0;
    {
        int t = tid;
        while (ti < 16 && t >= 16 - ti) { t -= 16 - ti; ti++; }
        tj = ti + t;
    }
    bool active = (tid < 136);

    float C[4][4];
    #pragma unroll
    for (int r = 0; r < 4; r++)
        #pragma unroll
        for (int c = 0; c < 4; c++) C[r][c] = 0.f;

    __syncthreads();

    for (int tl = blockIdx.x; tl < NG/128; tl += gridDim.x) {
        long base = ((long)b*NG + (long)tl*128) * NA;
        for (int i = tid; i < 128*16; i += 160) {
            int p = i >> 4, c = i & 15;
            float4 dv = *(const float4*)(dist + base + (long)p*NA + 4*c);
            float4 gv;
            gv.x = gto_val(dv.x, qs[4*c+0], zs[4*c+0]);
            gv.y = gto_val(dv.y, qs[4*c+1], zs[4*c+1]);
            gv.z = gto_val(dv.z, qs[4*c+2], zs[4*c+2]);
            gv.w = gto_val(dv.w, qs[4*c+3], zs[4*c+3]);
            *(float4*)&tile[p*68 + 4*c] = gv;
        }
        __syncthreads();
        if (active) {
            #pragma unroll 4
            for (int k = 0; k < 128; k++) {
                float4 ai = *(const float4*)&tile[k*68 + 4*ti];
                float4 aj = *(const float4*)&tile[k*68 + 4*tj];
                fma4(C[0], ai.x, aj); fma4(C[1], ai.y, aj);
                fma4(C[2], ai.z, aj); fma4(C[3], ai.w, aj);
            }
        }
        __syncthreads();
    }

    if (active) {
        float* Gb = g_G + b*4096;
        if (ti == tj) {
            #pragma unroll
            for (int r = 0; r < 4; r++)
                #pragma unroll
                for (int c = 0; c < 4; c++)
                    atomicAdd(&Gb[(4*ti + r)*64 + 4*tj + c], C[r][c]);
        } else {
            #pragma unroll
            for (int r = 0; r < 4; r++)
                #pragma unroll
                for (int c = 0; c < 4; c++) {
                    atomicAdd(&Gb[(4*ti + r)*64 + 4*tj + c], C[r][c]);
                    atomicAdd(&Gb[(4*tj + c)*64 + 4*ti + r], C[r][c]);
                }
        }
    }
}

// ---------- fused prep: ceff -> monorm -> packed M ----------
#define PF_SMEM ((4096 + 8448 + 64 + 128 + 128 + 256) * 4 + 64*4)
__global__ void __launch_bounds__(256) prepFK(const int* __restrict__ ao,
                                              const float* __restrict__ coef,
                                              const float* __restrict__ Ne) {
    extern __shared__ float sm[];
    float* Gs    = sm;                    // 4096
    float* ceffS = Gs + 4096;             // 64*132
    float* rg    = ceffS + 8448;          // 64
    float* rc    = rg + 64;               // 128
    float* inv   = rc + 128;              // 128
    float* mpart = inv + 128;             // 256
    int*   aos   = (int*)(mpart + 256);   // 64
    int b = blockIdx.x, tid = threadIdx.x;

    for (int i = tid; i < 4096; i += 256) Gs[i] = g_G[b*4096 + i];
    if (tid < 64) aos[tid] = ao[b*NA + tid];
    __syncthreads();
    if (tid < 64) rg[tid] = 1.f / fmaxf(sqrtf(Gs[tid*64 + tid]), 1e-12f);

    for (int i = tid; i < 64*128; i += 256) {
        int a = i >> 7, d = i & 127;
        ceffS[a*132 + d] = coef[aos[a]*ND + d];
    }
    __syncthreads();

    if (tid < 128) {
        float cn = 0.f;
        #pragma unroll 8
        for (int a = 0; a < 64; a++) { float c = ceffS[a*132 + tid]; cn = fmaf(c, c, cn); }
        rc[tid] = 1.f / fmaxf(sqrtf(cn), 1e-12f);
    }
    __syncthreads();
    for (int i = tid; i < 64*128; i += 256) {
        int a = i >> 7, d = i & 127;
        ceffS[a*132 + d] *= rc[d] * rg[a];
    }
    __syncthreads();

    {
        int d = tid & 127, h = tid >> 7;
        float c[64];
        #pragma unroll
        for (int a = 0; a < 64; a++) c[a] = ceffS[a*132 + d];
        float m = 0.f;
        int i0 = 32*h;
        for (int i = i0; i < i0 + 32; i++) {
            const float4* row = (const float4*)&Gs[i*64];
            float y0 = 0.f, y1 = 0.f, y2 = 0.f, y3 = 0.f;
            #pragma unroll
            for (int k = 0; k < 4; k++) {
                float4 ga = row[k],     gb = row[k+4];
                float4 gc = row[k+8],   gd = row[k+12];
                y0 = fmaf(ga.x, c[4*k+0],  y0); y0 = fmaf(ga.y, c[4*k+1],  y0);
                y0 = fmaf(ga.z, c[4*k+2],  y0); y0 = fmaf(ga.w, c[4*k+3],  y0);
                y1 = fmaf(gb.x, c[16+4*k+0], y1); y1 = fmaf(gb.y, c[16+4*k+1], y1);
                y1 = fmaf(gb.z, c[16+4*k+2], y1); y1 = fmaf(gb.w, c[16+4*k+3], y1);
                y2 = fmaf(gc.x, c[32+4*k+0], y2); y2 = fmaf(gc.y, c[32+4*k+1], y2);
                y2 = fmaf(gc.z, c[32+4*k+2], y2); y2 = fmaf(gc.w, c[32+4*k+3], y2);
                y3 = fmaf(gd.x, c[48+4*k+0], y3); y3 = fmaf(gd.y, c[48+4*k+1], y3);
                y3 = fmaf(gd.z, c[48+4*k+2], y3); y3 = fmaf(gd.w, c[48+4*k+3], y3);
            }
            m = fmaf(y0 + y1 + y2 + y3, c[i], m);
        }
        mpart[h*128 + d] = m;
    }
    __syncthreads();
    if (tid < 128) {
        float m = mpart[tid] + mpart[128 + tid];
        float s2 = Ne[b] / (float)ND;
        inv[tid] = sqrtf(s2 / fmaxf(m, 1e-24f));
    }
    __syncthreads();
    for (int i = tid; i < 64*128; i += 256) {
        int a = i >> 7, d = i & 127;
        ceffS[a*132 + d] *= inv[d];
    }
    __syncthreads();

    if (tid < NTILE_SYM) {
        int ti = 0, tj = 0;
        {
            int t = tid;
            while (ti < 16 && t >= 16 - ti) { t -= 16 - ti; ti++; }
            tj = ti + t;
        }
        float acc[4][4];
        #pragma unroll
        for (int r = 0; r < 4; r++)
            #pragma unroll
            for (int c = 0; c < 4; c++) acc[r][c] = 0.f;
        for (int d = 0; d < 128; d++) {
            float ci[4], cj[4];
            #pragma unroll
            for (int r = 0; r < 4; r++) ci[r] = ceffS[(4*ti + r)*132 + d];
            #pragma unroll
            for (int c = 0; c < 4; c++) cj[c] = ceffS[(4*tj + c)*132 + d];
            #pragma unroll
            for (int r = 0; r < 4; r++)
                #pragma unroll
                for (int c = 0; c < 4; c++) acc[r][c] = fmaf(ci[r], cj[c], acc[r][c]);
        }
        float sc = (ti == tj) ? 1.0f : 2.0f;
        float* dst = g_Mpk + b*NTILE_SYM*16 + tid*16;
        #pragma unroll
        for (int r = 0; r < 4; r++)
            #pragma unroll
            for (int c = 0; c < 4; c++) dst[r*4 + c] = acc[r][c] * sc;
    }
}

// ---------- pass 2: dens = g^T M g, thread-pair per point, 2 points/thread ----------
#define DQ_SMEM ((DQP*68 + NTILE_SYM*16 + 64 + DQP) * 4 + 64*4)
__global__ void __launch_bounds__(128, 5) densQK(const float* __restrict__ dist,
                                                 const int* __restrict__ qn,
                                                 const int* __restrict__ ao,
                                                 const float* __restrict__ zeta) {
    extern __shared__ float sm[];
    float* gt = sm;                        // [DQP][68]
    float* Mp = gt + DQP*68;               // 2176
    float* zs = Mp + NTILE_SYM*16;         // 64
    float* pd = zs + 64;                   // DQP partials
    int*   qs = (int*)(pd + DQP);          // 64
    int tid = threadIdx.x;
    int b   = blockIdx.y;
    int g0  = blockIdx.x * DQP;
    int p   = tid & 63;                    // point pair: p and p+64
    int h   = tid >> 6;                    // warp-uniform half id

    if (tid < 64) {
        qs[tid] = qn[b*NA + tid];
        zs[tid] = zeta[ao[b*NA + tid]];
    }
    for (int i = tid; i < NTILE_SYM*16; i += 128) Mp[i] = g_Mpk[b*NTILE_SYM*16 + i];
    __syncthreads();

    long base = ((long)b*NG + g0) * NA;
    for (int i = tid; i < DQP*16; i += 128) {
        int pp = i >> 4, c = i & 15;
        float4 dv = *(const float4*)(dist + base + (long)pp*NA + 4*c);
        float4 gv;
        gv.x = gto_val(dv.x, qs[4*c+0], zs[4*c+0]);
        gv.y = gto_val(dv.y, qs[4*c+1], zs[4*c+1]);
        gv.z = gto_val(dv.z, qs[4*c+2], zs[4*c+2]);
        gv.w = gto_val(dv.w, qs[4*c+3], zs[4*c+3]);
        *(float4*)&gt[pp*68 + 4*c] = gv;
    }
    __syncthreads();

    // own halves of both points into registers
    float ga[32], gb[32];
    {
        const float* gp0 = gt + p*68 + 32*h;
        const float* gp1 = gt + (p + 64)*68 + 32*h;
        #pragma unroll
        for (int k = 0; k < 8; k++) {
            float4 v0 = *(const float4*)(gp0 + 4*k);
            float4 v1 = *(const float4*)(gp1 + 4*k);
            ga[4*k+0] = v0.x; ga[4*k+1] = v0.y; ga[4*k+2] = v0.z; ga[4*k+3] = v0.w;
            gb[4*k+0] = v1.x; gb[4*k+1] = v1.y; gb[4*k+2] = v1.z; gb[4*k+3] = v1.w;
        }
    }

    const float4* Mt = (const float4*)Mp;
    float densA = 0.f, densB = 0.f;

    // own-half symmetric QF: tiles (8h+a, 8h+bb), a<=bb  -- one M load, both points
    #pragma unroll
    for (int a = 0; a < 8; a++) {
        float y0 = 0.f, y1 = 0.f, y2 = 0.f, y3 = 0.f;
        float z0 = 0.f, z1 = 0.f, z2 = 0.f, z3 = 0.f;
        #pragma unroll
        for (int bb = a; bb < 8; bb++) {
            int t = tsym(8*h + a, 8*h + bb);
            float4 m0 = Mt[4*t+0], m1 = Mt[4*t+1], m2 = Mt[4*t+2], m3 = Mt[4*t+3];
            float a0 = ga[4*bb+0], a1 = ga[4*bb+1], a2 = ga[4*bb+2], a3 = ga[4*bb+3];
            float b0 = gb[4*bb+0], b1 = gb[4*bb+1], b2 = gb[4*bb+2], b3 = gb[4*bb+3];
            y0 = fmaf(m0.x, a0, y0); y0 = fmaf(m0.y, a1, y0);
            y0 = fmaf(m0.z, a2, y0); y0 = fmaf(m0.w, a3, y0);
            y1 = fmaf(m1.x, a0, y1); y1 = fmaf(m1.y, a1, y1);
            y1 = fmaf(m1.z, a2, y1); y1 = fmaf(m1.w, a3, y1);
            y2 = fmaf(m2.x, a0, y2); y2 = fmaf(m2.y, a1, y2);
            y2 = fmaf(m2.z, a2, y2); y2 = fmaf(m2.w, a3, y2);
            y3 = fmaf(m3.x, a0, y3); y3 = fmaf(m3.y, a1, y3);
            y3 = fmaf(m3.z, a2, y3); y3 = fmaf(m3.w, a3, y3);
            z0 = fmaf(m0.x, b0, z0); z0 = fmaf(m0.y, b1, z0);
            z0 = fmaf(m0.z, b2, z0); z0 = fmaf(m0.w, b3, z0);
            z1 = fmaf(m1.x, b0, z1); z1 = fmaf(m1.y, b1, z1);
            z1 = fmaf(m1.z, b2, z1); z1 = fmaf(m1.w, b3, z1);
            z2 = fmaf(m2.x, b0, z2); z2 = fmaf(m2.y, b1, z2);
            z2 = fmaf(m2.z, b2, z2); z2 = fmaf(m2.w, b3, z2);
            z3 = fmaf(m3.x, b0, z3); z3 = fmaf(m3.y, b1, z3);
            z3 = fmaf(m3.z, b2, z3); z3 = fmaf(m3.w, b3, z3);
        }
        float sA = ga[4*a+0]*y0 + ga[4*a+1]*y1;
        sA = fmaf(ga[4*a+2], y2, sA);
        sA = fmaf(ga[4*a+3], y3, sA);
        densA += sA;
        float sB = gb[4*a+0]*z0 + gb[4*a+1]*z1;
        sB = fmaf(gb[4*a+2], z2, sB);
        sB = fmaf(gb[4*a+3], z3, sB);
        densB += sB;
    }

    // cross block: tiles (a, 8+bb) -- split by half, one M load serves both points
    if (h == 0) {
        #pragma unroll
        for (int bb = 0; bb < 4; bb++) {
            float4 gjA = *(const float4*)&gt[p*68 + 32 + 4*bb];
            float4 gjB = *(const float4*)&gt[(p + 64)*68 + 32 + 4*bb];
            float w0 = 0.f, w1 = 0.f, w2 = 0.f, w3 = 0.f;
            float x0 = 0.f, x1 = 0.f, x2 = 0.f, x3 = 0.f;
            #pragma unroll
            for (int a = 0; a < 8; a++) {
                int t = tsym(a, 8 + bb);
                float4 m0 = Mt[4*t+0], m1 = Mt[4*t+1], m2 = Mt[4*t+2], m3 = Mt[4*t+3];
                float a0 = ga[4*a+0], a1 = ga[4*a+1], a2 = ga[4*a+2], a3 = ga[4*a+3];
                float b0 = gb[4*a+0], b1 = gb[4*a+1], b2 = gb[4*a+2], b3 = gb[4*a+3];
                w0 = fmaf(m0.x, a0, w0); w1 = fmaf(m0.y, a0, w1);
                w2 = fmaf(m0.z, a0, w2); w3 = fmaf(m0.w, a0, w3);
                w0 = fmaf(m1.x, a1, w0); w1 = fmaf(m1.y, a1, w1);
                w2 = fmaf(m1.z, a1, w2); w3 = fmaf(m1.w, a1, w3);
                w0 = fmaf(m2.x, a2, w0); w1 = fmaf(m2.y, a2, w1);
                w2 = fmaf(m2.z, a2, w2); w3 = fmaf(m2.w, a2, w3);
                w0 = fmaf(m3.x, a3, w0); w1 = fmaf(m3.y, a3, w1);
                w2 = fmaf(m3.z, a3, w2); w3 = fmaf(m3.w, a3, w3);
                x0 = fmaf(m0.x, b0, x0); x1 = fmaf(m0.y, b0, x1);
                x2 = fmaf(m0.z, b0, x2); x3 = fmaf(m0.w, b0, x3);
                x0 = fmaf(m1.x, b1, x0); x1 = fmaf(m1.y, b1, x1);
                x2 = fmaf(m1.z, b1, x2); x3 = fmaf(m1.w, b1, x3);
                x0 = fmaf(m2.x, b2, x0); x1 = fmaf(m2.y, b2, x1);
                x2 = fmaf(m2.z, b2, x2); x3 = fmaf(m2.w, b2, x3);
                x0 = fmaf(m3.x, b3, x0); x1 = fmaf(m3.y, b3, x1);
                x2 = fmaf(m3.z, b3, x2); x3 = fmaf(m3.w, b3, x3);
            }
            float sA = w0*gjA.x + w1*gjA.y;
            sA = fmaf(w2, gjA.z, sA);
            sA = fmaf(w3, gjA.w, sA);
            densA += sA;
            float sB = x0*gjB.x + x1*gjB.y;
            sB = fmaf(x2, gjB.z, sB);
            sB = fmaf(x3, gjB.w, sB);
            densB += sB;
        }
    } else {
        #pragma unroll
        for (int a = 0; a < 8; a++) {
            float v0 = 0.f, v1 = 0.f, v2 = 0.f, v3 = 0.f;
            float u0 = 0.f, u1 = 0.f, u2 = 0.f, u3 = 0.f;
            #pragma unroll
            for (int bb = 4; bb < 8; bb++) {
                int t = tsym(a, 8 + bb);
                float4 m0 = Mt[4*t+0], m1 = Mt[4*t+1], m2 = Mt[4*t+2], m3 = Mt[4*t+3];
                float a0 = ga[4*bb+0], a1 = ga[4*bb+1], a2 = ga[4*bb+2], a3 = ga[4*bb+3];
                float b0 = gb[4*bb+0], b1 = gb[4*bb+1], b2 = gb[4*bb+2], b3 = gb[4*bb+3];
                v0 = fmaf(m0.x, a0, v0); v0 = fmaf(m0.y, a1, v0);
                v0 = fmaf(m0.z, a2, v0); v0 = fmaf(m0.w, a3, v0);
                v1 = fmaf(m1.x, a0, v1); v1 = fmaf(m1.y, a1, v1);
                v1 = fmaf(m1.z, a2, v1); v1 = fmaf(m1.w, a3, v1);
                v2 = fmaf(m2.x, a0, v2); v2 = fmaf(m2.y, a1, v2);
                v2 = fmaf(m2.z, a2, v2); v2 = fmaf(m2.w, a3, v2);
                v3 = fmaf(m3.x, a0, v3); v3 = fmaf(m3.y, a1, v3);
                v3 = fmaf(m3.z, a2, v3); v3 = fmaf(m3.w, a3, v3);
                u0 = fmaf(m0.x, b0, u0); u0 = fmaf(m0.y, b1, u0);
                u0 = fmaf(m0.z, b2, u0); u0 = fmaf(m0.w, b3, u0);
                u1 = fmaf(m1.x, b0, u1); u1 = fmaf(m1.y, b1, u1);
                u1 = fmaf(m1.z, b2, u1); u1 = fmaf(m1.w, b3, u1);
                u2 = fmaf(m2.x, b0, u2); u2 = fmaf(m2.y, b1, u2);
                u2 = fmaf(m2.z, b2, u2); u2 = fmaf(m2.w, b3, u2);
                u3 = fmaf(m3.x, b0, u3); u3 = fmaf(m3.y, b1, u3);
                u3 = fmaf(m3.z, b2, u3); u3 = fmaf(m3.w, b3, u3);
            }
            float4 giA = *(const float4*)&gt[p*68 + 4*a];
            float4 giB = *(const float4*)&gt[(p + 64)*68 + 4*a];
            float sA = giA.x*v0 + giA.y*v1;
            sA = fmaf(giA.z, v2, sA);
            sA = fmaf(giA.w, v3, sA);
            densA += sA;
            float sB = giB.x*u0 + giB.y*u1;
            sB = fmaf(giB.z, u2, sB);
            sB = fmaf(giB.w, u3, sB);
            densB += sB;
        }
    }

    if (h == 1) { pd[p] = densA; pd[p + 64] = densB; }
    __syncthreads();
    if (h == 0) {
        float dA = densA + pd[p];
        float dB = densB + pd[p + 64];
        g_dens[(long)b*NG + g0 + p]      = dA;
        g_dens[(long)b*NG + g0 + p + 64] = dB;
        float mx = fmaxf(dA, dB);
        #pragma unroll
        for (int off = 16; off; off >>= 1)
            mx = fmaxf(mx, __shfl_xor_sync(0xffffffffu, mx, off));
        if ((tid & 31) == 0) atomicMax(&g_densmax_u, __float_as_uint(mx));
    }
}

// ---------- table: phi at NT_TAB nodes over [0, densmax] ----------
__global__ void __launch_bounds__(256) tableK(const float* __restrict__ wfb,
                                              const float* __restrict__ wpw) {
    extern __shared__ float sm[];
    float* W1   = sm;
    float* W2   = W1 + ND*ND;
    float* bufA = W2 + ND*ND;
    float* bufB = bufA + GT*ND;
    float* us   = bufB + GT*BSTRIDE;
    float* ts   = us  + ND;
    float* b1s  = ts  + ND;
    float* b2s  = b1s + ND;
    float* wps  = b2s + ND;
    int tid = threadIdx.x;

    for (int i = tid; i < ND*ND; i += 256) { W1[i] = g_W1t[i]; W2[i] = g_W2t[i]; }
    if (tid < ND) {
        us[tid]  = g_u[tid];
        ts[tid]  = g_t[tid];
        b1s[tid] = wfb[ND + tid];
        b2s[tid] = wfb[2*ND + tid];
        wps[tid] = wpw[tid];
    }
    float h = __uint_as_float(g_densmax_u) / (float)(NT_TAB - 1);
    __syncthreads();

    int t0 = blockIdx.x * GT;
    for (int i = tid; i < GT*ND; i += 256) {
        int g = i >> 7, e = i & 127;
        float x = (float)(t0 + g) * h;
        bufA[i] = fmaxf(fmaf(x, us[e], ts[e]), 0.f);
    }
    __syncthreads();

    int eq = tid & 31, gq = tid >> 5;
    float acc[8][4];
    {
        float4 bb = *(const float4*)&b1s[4*eq];
        #pragma unroll
        for (int r = 0; r < 8; r++) { acc[r][0]=bb.x; acc[r][1]=bb.y; acc[r][2]=bb.z; acc[r][3]=bb.w; }
    }
    #pragma unroll 4
    for (int d4 = 0; d4 < 32; d4++) {
        float4 w[4];
        #pragma unroll
        for (int k = 0; k < 4; k++) w[k] = *(const float4*)&W1[(4*d4 + k)*ND + 4*eq];
        #pragma unroll
        for (int r = 0; r < 8; r++) {
            float4 v = *(const float4*)&bufA[(gq*8 + r)*ND + 4*d4];
            fma4(acc[r], v.x, w[0]); fma4(acc[r], v.y, w[1]);
            fma4(acc[r], v.z, w[2]); fma4(acc[r], v.w, w[3]);
        }
    }
    #pragma unroll
    for (int r = 0; r < 8; r++) {
        float4 o = make_float4(fmaxf(acc[r][0],0.f), fmaxf(acc[r][1],0.f),
                               fmaxf(acc[r][2],0.f), fmaxf(acc[r][3],0.f));
        *(float4*)&bufB[(gq*8 + r)*BSTRIDE + 4*eq] = o;
    }
    __syncthreads();

    {
        float4 bb = *(const float4*)&b2s[4*eq];
        #pragma unroll
        for (int r = 0; r < 8; r++) { acc[r][0]=bb.x; acc[r][1]=bb.y; acc[r][2]=bb.z; acc[r][3]=bb.w; }
    }
    #pragma unroll 4
    for (int d4 = 0; d4 < 32; d4++) {
        float4 w[4];
        #pragma unroll
        for (int k = 0; k < 4; k++) w[k] = *(const float4*)&W2[(4*d4 + k)*ND + 4*eq];
        #pragma unroll
        for (int r = 0; r < 8; r++) {
            float4 v = *(const float4*)&bufB[(gq*8 + r)*BSTRIDE + 4*d4];
            fma4(acc[r], v.x, w[0]); fma4(acc[r], v.y, w[1]);
            fma4(acc[r], v.z, w[2]); fma4(acc[r], v.w, w[3]);
        }
    }
    float4 wp4 = *(const float4*)&wps[4*eq];
    #pragma unroll
    for (int r = 0; r < 8; r++) {
        float v = fmaxf(acc[r][0],0.f)*wp4.x + fmaxf(acc[r][1],0.f)*wp4.y
                + fmaxf(acc[r][2],0.f)*wp4.z + fmaxf(acc[r][3],0.f)*wp4.w;
        #pragma unroll
        for (int off = 16; off; off >>= 1) v += __shfl_xor_sync(0xffffffffu, v, off);
        if (eq == 0) g_table[t0 + gq*8 + r] = v;
    }
}

// ---------- final: E[b] += sum_g lerp(table, dens) ----------
__global__ void __launch_bounds__(256) sumK(float* __restrict__ out) {
    extern __shared__ float T[];
    float* red = T + NT_TAB;
    int tid = threadIdx.x;
    for (int i = tid; i < NT_TAB/4; i += 256)
        ((float4*)T)[i] = ((const float4*)g_table)[i];
    __syncthreads();
    float invh = (float)(NT_TAB - 1) / __uint_as_float(g_densmax_u);
    int b = blockIdx.y;
    const int chunk = NG / 8;
    long base = (long)b*NG + blockIdx.x*chunk;
    float acc = 0.f;
    for (int i = tid; i < chunk; i += 256) {
        float dn = g_dens[base + i];
        float t  = dn * invh;
        int ix = min((int)t, NT_TAB - 2);
        float f = t - (float)ix;
        acc += fmaf(f, T[ix+1] - T[ix], T[ix]);
    }
    #pragma unroll
    for (int off = 16; off; off >>= 1) acc += __shfl_xor_sync(0xffffffffu, acc, off);
    if ((tid & 31) == 0) red[tid >> 5] = acc;
    __syncthreads();
    if (tid == 0) {
        float s = 0.f;
        #pragma unroll
        for (int w = 0; w < 8; w++) s += red[w];
        atomicAdd(&out[b], s);
    }
}

extern "C" void kernel_launch(void* const* d_in, const int* in_sizes, int n_in,
                              void* d_out, int out_size) {
    const float* dist  = (const float*)d_in[0];
    const int*   qn    = (const int*)  d_in[1];
    const int*   ao    = (const int*)  d_in[2];
    const float* Ne    = (const float*)d_in[3];
    const float* coef  = (const float*)d_in[4];
    const float* zeta  = (const float*)d_in[5];
    const float* wprew = (const float*)d_in[6];
    const float* wpreb = (const float*)d_in[7];
    const float* wfw   = (const float*)d_in[8];
    const float* wfb   = (const float*)d_in[9];
    const float* wpw   = (const float*)d_in[10];
    const float* wpb   = (const float*)d_in[11];
    float* out = (float*)d_out;

    const int tabSmem = (ND*ND*2 + GT*ND + GT*BSTRIDE + ND*5) * 4;
    const int sumSmem = (NT_TAB + 8) * 4;
    cudaFuncSetAttribute(gtoGK,  cudaFuncAttributeMaxDynamicSharedMemorySize, G_SMEM);
    cudaFuncSetAttribute(prepFK, cudaFuncAttributeMaxDynamicSharedMemorySize, PF_SMEM);
    cudaFuncSetAttribute(densQK, cudaFuncAttributeMaxDynamicSharedMemorySize, DQ_SMEM);
    cudaFuncSetAttribute(tableK, cudaFuncAttributeMaxDynamicSharedMemorySize, tabSmem);
    cudaFuncSetAttribute(sumK,   cudaFuncAttributeMaxDynamicSharedMemorySize, sumSmem);

    setupK<<<12, 256>>>(out, wpb, wprew, wpreb, wfw, wfb);
    gtoGK<<<dim3(111, NB), 160, G_SMEM>>>(dist, qn, ao, zeta);
    prepFK<<<NB, 256, PF_SMEM>>>(ao, coef, Ne);
    densQK<<<dim3(NG/DQP, NB), 128, DQ_SMEM>>>(dist, qn, ao, zeta);
    tableK<<<NT_TAB/GT, 256, tabSmem>>>(wfb, wpw);
    sumK<<<dim3(8, NB), 256, sumSmem>>>(out);
}